// round 1
// baseline (speedup 1.0000x reference)
#include <cuda_runtime.h>
#include <cuda_bf16.h>
#include <math.h>

// ---------------- model constants ----------------
#define Dm    256
#define Hn    8
#define DHn   32
#define Ln    64
#define BEHn  2
#define SPKn  64
#define NLn   2
#define Bn    16
#define EMAXC 13568          // max_events cap (53*256)
#define CHUNKE 256           // events per cross-attn chunk
#define NCHUNK 53            // 53*256 = 13568
#define EMAXE 200000         // event buffer capacity
#define NTH   2048           // threads for deterministic bucket scan

#define SCALE 0.17677669529663687f   // 1/sqrt(32)

// ---------------- scratch (device globals; no allocation allowed) ----------------
__device__ float g_tok[(size_t)EMAXE * Dm];          // LN'd token embeddings
__device__ float g_kv [(size_t)EMAXE * 2 * Dm];      // K|V per event
__device__ int   g_order[EMAXE];
__device__ int   g_hist[NTH * Bn];
__device__ int   g_cnt[Bn];
__device__ int   g_off[Bn];
__device__ float g_psum[Bn * NCHUNK * 512];
__device__ float g_pv [(size_t)Bn * NCHUNK * 512 * 32];
__device__ float g_q   [Ln * Dm];
__device__ float g_x   [Bn * Ln * Dm];
__device__ float g_qkv [Bn * Ln * 3 * Dm];
__device__ float g_hbuf[Bn * Ln * 4 * Dm];
__device__ float g_ao  [Bn * Ln * Dm];
__device__ float g_lat [Bn * Ln * Dm];
__device__ float g_kvb [Bn * Ln * 2 * Dm];
__device__ float g_qb  [BEHn * Dm];

// ---------------- deterministic bucketing by batch ----------------
__global__ void hist_pass1(const int* __restrict__ bidx, int E) {
    int t = blockIdx.x * blockDim.x + threadIdx.x;
    int ch = (E + NTH - 1) / NTH;
    int s = t * ch, e = min(E, s + ch);
    int loc[Bn];
#pragma unroll
    for (int b = 0; b < Bn; b++) loc[b] = 0;
    for (int i = s; i < e; i++) loc[bidx[i] & (Bn - 1)]++;
#pragma unroll
    for (int b = 0; b < Bn; b++) g_hist[t * Bn + b] = loc[b];
}

__global__ void hist_scan() {
    __shared__ int tot[Bn], off[Bn];
    int b = threadIdx.x;
    if (b < Bn) {
        int run = 0;
        for (int t = 0; t < NTH; t++) {
            int v = g_hist[t * Bn + b];
            g_hist[t * Bn + b] = run;
            run += v;
        }
        tot[b] = run;
    }
    __syncthreads();
    if (threadIdx.x == 0) {
        int run = 0;
        for (int bb = 0; bb < Bn; bb++) { off[bb] = run; run += tot[bb]; }
    }
    __syncthreads();
    if (b < Bn) {
        g_cnt[b] = tot[b];
        g_off[b] = off[b];
        for (int t = 0; t < NTH; t++) g_hist[t * Bn + b] += off[b];
    }
}

__global__ void scatter_pass(const int* __restrict__ bidx, int E) {
    int t = blockIdx.x * blockDim.x + threadIdx.x;
    int ch = (E + NTH - 1) / NTH;
    int s = t * ch, e = min(E, s + ch);
    int base[Bn];
#pragma unroll
    for (int b = 0; b < Bn; b++) base[b] = g_hist[t * Bn + b];
    for (int i = s; i < e; i++) {
        int b = bidx[i] & (Bn - 1);
        g_order[base[b]++] = i;
    }
}

// ---------------- token embed + LN (warp per event) ----------------
__global__ void tok_kernel(const int* __restrict__ nid, const int* __restrict__ tb,
                           const int* __restrict__ vv,
                           const float* __restrict__ ne, const float* __restrict__ te,
                           const float* __restrict__ ve, int E) {
    int w = (blockIdx.x * blockDim.x + threadIdx.x) >> 5;
    int lane = threadIdx.x & 31;
    if (w >= E) return;
    const float* pn = ne + (size_t)nid[w] * Dm;
    const float* pt = te + (size_t)tb[w] * Dm;
    const float* pv = ve + (size_t)vv[w] * Dm;
    float v[8]; float sum = 0.f, sq = 0.f;
#pragma unroll
    for (int i = 0; i < 8; i++) {
        int c = lane + i * 32;
        v[i] = pn[c] + pt[c] + pv[c];
        sum += v[i]; sq += v[i] * v[i];
    }
#pragma unroll
    for (int o = 16; o > 0; o >>= 1) {
        sum += __shfl_xor_sync(~0u, sum, o);
        sq  += __shfl_xor_sync(~0u, sq,  o);
    }
    float mean = sum * (1.f / Dm);
    float var = sq * (1.f / Dm) - mean * mean;
    float rs = rsqrtf(var + 1e-5f);
    float* d = g_tok + (size_t)w * Dm;
#pragma unroll
    for (int i = 0; i < 8; i++) d[lane + i * 32] = (v[i] - mean) * rs;
}

// ---------------- LN over 256 (warp per row) ----------------
__global__ void ln_kernel(const float* __restrict__ src, float* __restrict__ dst,
                          const float* __restrict__ w, const float* __restrict__ bb, int rows) {
    int r = (blockIdx.x * blockDim.x + threadIdx.x) >> 5;
    int lane = threadIdx.x & 31;
    if (r >= rows) return;
    const float* s = src + (size_t)r * Dm;
    float v[8]; float sum = 0.f, sq = 0.f;
#pragma unroll
    for (int i = 0; i < 8; i++) {
        v[i] = s[lane + i * 32];
        sum += v[i]; sq += v[i] * v[i];
    }
#pragma unroll
    for (int o = 16; o > 0; o >>= 1) {
        sum += __shfl_xor_sync(~0u, sum, o);
        sq  += __shfl_xor_sync(~0u, sq,  o);
    }
    float mean = sum * (1.f / Dm);
    float var = sq * (1.f / Dm) - mean * mean;
    float rs = rsqrtf(var + 1e-5f);
    float* d = dst + (size_t)r * Dm;
#pragma unroll
    for (int i = 0; i < 8; i++) {
        int c = lane + i * 32;
        float y = (v[i] - mean) * rs;
        if (w) y = y * w[c] + bb[c];
        d[c] = y;
    }
}

// ---------------- generic fp32 GEMM: C = op(A@B [+res]) ----------------
// A: MxK row-major, B: KxN row-major. N % 64 == 0, K % 16 == 0.
// mode 0: C = AB; 1: C = res + AB; 2: C = gelu(AB)
__global__ __launch_bounds__(256) void gemm_kernel(
    const float* __restrict__ A, const float* __restrict__ B,
    const float* __restrict__ res, float* __restrict__ C,
    int M, int N, int K, int mode) {
    __shared__ float As[16][128];
    __shared__ float Bs[16][64];
    int bm = blockIdx.x * 128, bn = blockIdx.y * 64;
    int t = threadIdx.x;
    int ty = t >> 4, tx = t & 15;
    float acc[8][4];
#pragma unroll
    for (int i = 0; i < 8; i++)
#pragma unroll
        for (int j = 0; j < 4; j++) acc[i][j] = 0.f;

    for (int k0 = 0; k0 < K; k0 += 16) {
#pragma unroll
        for (int i = 0; i < 8; i++) {
            int idx = t + i * 256;
            int m = idx >> 4, k = idx & 15;
            int gm = bm + m;
            As[k][m] = (gm < M) ? A[(size_t)gm * K + k0 + k] : 0.f;
        }
#pragma unroll
        for (int i = 0; i < 4; i++) {
            int idx = t + i * 256;
            int k = idx >> 6, n = idx & 63;
            Bs[k][n] = B[(size_t)(k0 + k) * N + bn + n];
        }
        __syncthreads();
#pragma unroll
        for (int kk = 0; kk < 16; kk++) {
            float a[8], b4[4];
#pragma unroll
            for (int i = 0; i < 8; i++) a[i] = As[kk][ty * 8 + i];
#pragma unroll
            for (int j = 0; j < 4; j++) b4[j] = Bs[kk][tx * 4 + j];
#pragma unroll
            for (int i = 0; i < 8; i++)
#pragma unroll
                for (int j = 0; j < 4; j++) acc[i][j] = fmaf(a[i], b4[j], acc[i][j]);
        }
        __syncthreads();
    }
#pragma unroll
    for (int i = 0; i < 8; i++) {
        int gm = bm + ty * 8 + i;
        if (gm >= M) continue;
#pragma unroll
        for (int j = 0; j < 4; j++) {
            int gn = bn + tx * 4 + j;
            float v = acc[i][j];
            if (mode == 1) v += res[(size_t)gm * N + gn];
            else if (mode == 2) {
                float x = v;
                v = 0.5f * x * (1.f + tanhf(0.7978845608028654f * (x + 0.044715f * x * x * x)));
            }
            C[(size_t)gm * N + gn] = v;
        }
    }
}

// ---------------- cross-attention: chunk partials ----------------
// grid (Bn, NCHUNK), 512 threads; thread = (h,l) pair
__global__ __launch_bounds__(512) void xattn_kernel() {
    int b = blockIdx.x, c = blockIdx.y;
    int cnt = min(g_cnt[b], EMAXC);
    int start = g_off[b] + c * CHUNKE;
    int n = cnt - c * CHUNKE;
    if (n > CHUNKE) n = CHUNKE;
    if (n < 0) n = 0;

    int t = threadIdx.x;
    int h = t >> 6, l = t & 63;

    float qreg[32];
    const float* qp = g_q + l * Dm + h * DHn;
#pragma unroll
    for (int i = 0; i < 32; i++) qreg[i] = qp[i];

    float vacc[32];
#pragma unroll
    for (int i = 0; i < 32; i++) vacc[i] = 0.f;
    float se = 0.f;

    __shared__ float4 skv4[8 * 128];   // 8 events x 512 floats
    float* skv = (float*)skv4;

    for (int tile = 0; tile < n; tile += 8) {
        int ntile = n - tile; if (ntile > 8) ntile = 8;
        // stage 8x512 floats (1024 float4, 512 threads -> 2 passes)
#pragma unroll
        for (int pass = 0; pass < 2; pass++) {
            int idx = t + pass * 512;
            int e = idx >> 7, x = idx & 127;
            float4 val = make_float4(0.f, 0.f, 0.f, 0.f);
            if (e < ntile) {
                int ord = g_order[start + tile + e];
                val = ((const float4*)g_kv)[(size_t)ord * 128 + x];
            }
            skv4[idx] = val;
        }
        __syncthreads();
        for (int e = 0; e < ntile; e++) {
            const float* kk = skv + e * 512 + h * DHn;
            const float* vv = skv + e * 512 + 256 + h * DHn;
            float s = 0.f;
#pragma unroll
            for (int d = 0; d < 32; d++) s = fmaf(qreg[d], kk[d], s);
            float w = __expf(s * SCALE);
            se += w;
#pragma unroll
            for (int d = 0; d < 32; d++) vacc[d] = fmaf(w, vv[d], vacc[d]);
        }
        __syncthreads();
    }
    size_t base = (size_t)(b * NCHUNK + c) * 512 + t;
    g_psum[base] = se;
    float* pv = g_pv + base * 32;
#pragma unroll
    for (int d = 0; d < 32; d++) pv[d] = vacc[d];
}

// deterministic reduce over chunks; warp per (b, h, l)
__global__ void xreduce_kernel() {
    int g = blockIdx.x * 8 + (threadIdx.x >> 5);
    int lane = threadIdx.x & 31;
    int b = g >> 9, p = g & 511;
    float vs = 0.f, ss = 0.f;
    for (int c = 0; c < NCHUNK; c++) {
        size_t base = (size_t)(b * NCHUNK + c) * 512 + p;
        ss += g_psum[base];
        vs += g_pv[base * 32 + lane];
    }
    float o = vs / ss;
    int h = p >> 6, l = p & 63;
    g_ao[(size_t)(b * Ln + l) * Dm + h * DHn + lane] = o;
}

__global__ void bcast_lat(const float* __restrict__ lat_init) {
    int i = blockIdx.x * blockDim.x + threadIdx.x;
    if (i < Bn * Ln * Dm) g_lat[i] = lat_init[i & (Ln * Dm - 1)];
}

// ---------------- self-attention (64 latents), grid (Bn*Hn), 64 threads ----------------
__global__ __launch_bounds__(64) void selfattn_kernel() {
    int b = blockIdx.x >> 3, h = blockIdx.x & 7;
    __shared__ float ks[Ln * DHn], vs_[Ln * DHn], sc[Ln * Ln];
    int t = threadIdx.x;  // = query index l
    const float* rowq = g_qkv + (size_t)(b * Ln + t) * (3 * Dm);
    float q[32];
#pragma unroll
    for (int d = 0; d < 32; d++) {
        q[d] = rowq[h * DHn + d];
        ks[t * DHn + d]  = rowq[Dm + h * DHn + d];
        vs_[t * DHn + d] = rowq[2 * Dm + h * DHn + d];
    }
    __syncthreads();
    float m = -1e30f;
    for (int j = 0; j < Ln; j++) {
        float s = 0.f;
#pragma unroll
        for (int d = 0; d < 32; d++) s = fmaf(q[d], ks[j * DHn + d], s);
        s *= SCALE;
        sc[t * Ln + j] = s;
        m = fmaxf(m, s);
    }
    float sum = 0.f;
    for (int j = 0; j < Ln; j++) {
        float w = __expf(sc[t * Ln + j] - m);
        sc[t * Ln + j] = w;
        sum += w;
    }
    float inv = 1.f / sum;
    float o[32];
#pragma unroll
    for (int d = 0; d < 32; d++) o[d] = 0.f;
    for (int j = 0; j < Ln; j++) {
        float w = sc[t * Ln + j];
#pragma unroll
        for (int d = 0; d < 32; d++) o[d] = fmaf(w, vs_[j * DHn + d], o[d]);
    }
    float* dst = g_ao + (size_t)(b * Ln + t) * Dm + h * DHn;
#pragma unroll
    for (int d = 0; d < 32; d++) dst[d] = o[d] * inv;
}

// ---------------- behavior decoder attention + projection ----------------
__global__ __launch_bounds__(64) void bh_kernel(const float* __restrict__ wo, float* __restrict__ out) {
    int b = blockIdx.x, t = threadIdx.x;
    __shared__ float part[16];
    if (t < 16) {
        int qi = t >> 3, h = t & 7;
        float q[32];
#pragma unroll
        for (int d = 0; d < 32; d++) q[d] = g_qb[qi * Dm + h * DHn + d];
        float s[Ln];
        float m = -1e30f;
        for (int j = 0; j < Ln; j++) {
            const float* kp = g_kvb + (size_t)(b * Ln + j) * (2 * Dm) + h * DHn;
            float acc = 0.f;
#pragma unroll
            for (int d = 0; d < 32; d++) acc = fmaf(q[d], kp[d], acc);
            acc *= SCALE;
            s[j] = acc;
            m = fmaxf(m, acc);
        }
        float sum = 0.f;
        for (int j = 0; j < Ln; j++) { s[j] = __expf(s[j] - m); sum += s[j]; }
        float o[32];
#pragma unroll
        for (int d = 0; d < 32; d++) o[d] = 0.f;
        for (int j = 0; j < Ln; j++) {
            const float* vp = g_kvb + (size_t)(b * Ln + j) * (2 * Dm) + Dm + h * DHn;
            float w = s[j];
#pragma unroll
            for (int d = 0; d < 32; d++) o[d] = fmaf(w, vp[d], o[d]);
        }
        float inv = 1.f / sum;
        float partial = 0.f;
#pragma unroll
        for (int d = 0; d < 32; d++) partial += o[d] * inv * wo[h * DHn + d];
        part[t] = partial;
    }
    __syncthreads();
    if (t < BEHn) {
        float r = 0.f;
        for (int h = 0; h < Hn; h++) r += part[t * 8 + h];
        out[b * BEHn + t] = r;
    }
}

// ---------------- spike head: mean over L, then 256x64 ----------------
__global__ void spike_kernel(const float* __restrict__ spw, const float* __restrict__ spb,
                             float* __restrict__ out) {
    int b = blockIdx.x, t = threadIdx.x;
    __shared__ float mean[Dm];
    float acc = 0.f;
    for (int l = 0; l < Ln; l++) acc += g_lat[(size_t)(b * Ln + l) * Dm + t];
    mean[t] = acc * (1.f / Ln);
    __syncthreads();
    if (t < SPKn) {
        float r = spb[t];
        for (int d = 0; d < Dm; d++) r = fmaf(mean[d], spw[d * SPKn + t], r);
        out[Bn * BEHn + b * SPKn + t] = r;
    }
}

// ---------------- host ----------------
static inline void gemm(const float* A, const float* B, const float* res, float* C,
                        int M, int N, int K, int mode) {
    dim3 g((M + 127) / 128, N / 64);
    gemm_kernel<<<g, 256>>>(A, B, res, C, M, N, K, mode);
}

extern "C" void kernel_launch(void* const* d_in, const int* in_sizes, int n_in,
                              void* d_out, int out_size) {
    // Input-order hedge: dict order (neuron_ids first, size 200000) vs
    // reference-signature order (neuron_emb first, size 1048576).
    int map[27];
    if (in_sizes[0] < 1000000) {
        for (int i = 0; i < 27; i++) map[i] = i;  // dict order
    } else {
        // reference signature order -> dict slots
        // dict slots: 0 nid,1 tb,2 vals,3 bidx,4 bs,5 me,6 ne,7 te,8 ve,9 lat,10 Wq,11 Wkv,
        //             12 Wo,13 W1,14 W2,15 Wqkv_s,16 Wo_s,17 W1_s,18 W2_s,19 bhq,20 bhwq,
        //             21 bhwkv,22 bhwo,23 lnw,24 lnb,25 spw,26 spb
        int m2[27] = {21,22,23,24,25,26, 0,1,2,3,4,5,6,7,8,9,10,11,12,13,14,15,16,17,18,19,20};
        for (int i = 0; i < 27; i++) map[i] = m2[i];
    }
    const int*   nid  = (const int*)  d_in[map[0]];
    const int*   tbv  = (const int*)  d_in[map[1]];
    const int*   vals = (const int*)  d_in[map[2]];
    const int*   bidx = (const int*)  d_in[map[3]];
    const float* ne   = (const float*)d_in[map[6]];
    const float* te   = (const float*)d_in[map[7]];
    const float* ve   = (const float*)d_in[map[8]];
    const float* lat0 = (const float*)d_in[map[9]];
    const float* Wq   = (const float*)d_in[map[10]];
    const float* Wkv  = (const float*)d_in[map[11]];
    const float* Wo   = (const float*)d_in[map[12]];
    const float* W1   = (const float*)d_in[map[13]];
    const float* W2   = (const float*)d_in[map[14]];
    const float* Wqkv_s = (const float*)d_in[map[15]];
    const float* Wo_s   = (const float*)d_in[map[16]];
    const float* W1_s   = (const float*)d_in[map[17]];
    const float* W2_s   = (const float*)d_in[map[18]];
    const float* bhq    = (const float*)d_in[map[19]];
    const float* bhwq   = (const float*)d_in[map[20]];
    const float* bhwkv  = (const float*)d_in[map[21]];
    const float* bhwo   = (const float*)d_in[map[22]];
    const float* lnw    = (const float*)d_in[map[23]];
    const float* lnb    = (const float*)d_in[map[24]];
    const float* spw    = (const float*)d_in[map[25]];
    const float* spb    = (const float*)d_in[map[26]];
    int E = in_sizes[map[0]];
    if (E > EMAXE) E = EMAXE;
    float* out = (float*)d_out;

    void *p_tok, *p_kv, *p_q, *p_x, *p_qkv, *p_h, *p_ao, *p_lat, *p_kvb, *p_qb;
    cudaGetSymbolAddress(&p_tok, g_tok);
    cudaGetSymbolAddress(&p_kv,  g_kv);
    cudaGetSymbolAddress(&p_q,   g_q);
    cudaGetSymbolAddress(&p_x,   g_x);
    cudaGetSymbolAddress(&p_qkv, g_qkv);
    cudaGetSymbolAddress(&p_h,   g_hbuf);
    cudaGetSymbolAddress(&p_ao,  g_ao);
    cudaGetSymbolAddress(&p_lat, g_lat);
    cudaGetSymbolAddress(&p_kvb, g_kvb);
    cudaGetSymbolAddress(&p_qb,  g_qb);
    float* f_tok = (float*)p_tok; float* f_kv = (float*)p_kv; float* f_q = (float*)p_q;
    float* f_x = (float*)p_x; float* f_qkv = (float*)p_qkv; float* f_h = (float*)p_h;
    float* f_ao = (float*)p_ao; float* f_lat = (float*)p_lat; float* f_kvb = (float*)p_kvb;
    float* f_qb = (float*)p_qb;

    // 1) deterministic bucket-by-batch
    hist_pass1<<<NTH / 256, 256>>>(bidx, E);
    hist_scan<<<1, 32>>>();
    scatter_pass<<<NTH / 256, 256>>>(bidx, E);

    // 2) token embeddings + LN  (warp per event)
    tok_kernel<<<(E + 7) / 8, 256>>>(nid, tbv, vals, ne, te, ve, E);

    // 3) K,V projection of all events  (dominant GEMM: E x 512 x 256)
    gemm(f_tok, Wkv, nullptr, f_kv, E, 2 * Dm, Dm, 0);

    // 4) Q (identical for all batches): LN(lat_init) @ Wq_c
    ln_kernel<<<8, 256>>>(lat0, f_x, nullptr, nullptr, Ln);
    gemm(f_x, Wq, nullptr, f_q, Ln, Dm, Dm, 0);

    // 5) cross-attention partials + deterministic reduce
    xattn_kernel<<<dim3(Bn, NCHUNK), 512>>>();
    xreduce_kernel<<<Bn * 512 / 8, 256>>>();

    // 6) residual stream
    bcast_lat<<<(Bn * Ln * Dm) / 256, 256>>>(lat0);
    gemm(f_ao, Wo, f_lat, f_lat, Bn * Ln, Dm, Dm, 1);

    // 7) cross-block MLP
    ln_kernel<<<(Bn * Ln) / 8, 256>>>(f_lat, f_x, nullptr, nullptr, Bn * Ln);
    gemm(f_x, W1, nullptr, f_h, Bn * Ln, 4 * Dm, Dm, 2);
    gemm(f_h, W2, f_lat, f_lat, Bn * Ln, Dm, 4 * Dm, 1);

    // 8) self-attention blocks
    for (int i = 0; i < NLn; i++) {
        ln_kernel<<<(Bn * Ln) / 8, 256>>>(f_lat, f_x, nullptr, nullptr, Bn * Ln);
        gemm(f_x, Wqkv_s + (size_t)i * Dm * 3 * Dm, nullptr, f_qkv, Bn * Ln, 3 * Dm, Dm, 0);
        selfattn_kernel<<<Bn * Hn, 64>>>();
        gemm(f_ao, Wo_s + (size_t)i * Dm * Dm, f_lat, f_lat, Bn * Ln, Dm, Dm, 1);
        ln_kernel<<<(Bn * Ln) / 8, 256>>>(f_lat, f_x, nullptr, nullptr, Bn * Ln);
        gemm(f_x, W1_s + (size_t)i * Dm * 4 * Dm, nullptr, f_h, Bn * Ln, 4 * Dm, Dm, 2);
        gemm(f_h, W2_s + (size_t)i * 4 * Dm * Dm, f_lat, f_lat, Bn * Ln, Dm, 4 * Dm, 1);
    }

    // 9) behavior decoder
    ln_kernel<<<(Bn * Ln) / 8, 256>>>(f_lat, f_x, lnw, lnb, Bn * Ln);
    gemm(f_x, bhwkv, nullptr, f_kvb, Bn * Ln, 2 * Dm, Dm, 0);
    gemm(bhq, bhwq, nullptr, f_qb, BEHn, Dm, Dm, 0);
    bh_kernel<<<Bn, 64>>>(bhwo, out);

    // 10) spike head
    spike_kernel<<<Bn, 256>>>(spw, spb, out);
}

// round 2
// speedup vs baseline: 1.9193x; 1.9193x over previous
#include <cuda_runtime.h>
#include <cuda_bf16.h>
#include <math.h>

// ---------------- model constants ----------------
#define Dm    256
#define Hn    8
#define DHn   32
#define Ln    64
#define BEHn  2
#define SPKn  64
#define NLn   2
#define Bn    16
#define NEURONSn 4096
#define TBINSn   1024
#define VBUCKn   256
#define EMAXC 13568          // max_events cap (53*256)
#define CHUNKE 256           // events per cross-attn chunk
#define NCHUNK 53            // 53*256 = 13568
#define EMAXE 200000         // event buffer capacity
#define NTH   2048           // threads for deterministic bucket scan

#define SCALE 0.17677669529663687f   // 1/sqrt(32)

// ---------------- scratch (device globals; no allocation allowed) ----------------
__device__ float g_nkv[(size_t)NEURONSn * 2 * Dm];   // neuron_emb @ Wkv
__device__ float g_tkv[(size_t)TBINSn   * 2 * Dm];   // time_emb   @ Wkv
__device__ float g_vkv[(size_t)VBUCKn   * 2 * Dm];   // value_emb  @ Wkv
__device__ float g_csum[2 * Dm];                     // 1^T Wkv
__device__ float g_mu[EMAXE];
__device__ float g_rs[EMAXE];
__device__ int   g_order[EMAXE];
__device__ int   g_hist[NTH * Bn];
__device__ int   g_cnt[Bn];
__device__ int   g_off[Bn];
__device__ float g_psum[Bn * NCHUNK * 512];
__device__ float g_pv [(size_t)Bn * NCHUNK * 512 * 32];
__device__ float g_q   [Ln * Dm];
__device__ float g_x   [Bn * Ln * Dm];
__device__ float g_qkv [Bn * Ln * 3 * Dm];
__device__ float g_hbuf[Bn * Ln * 4 * Dm];
__device__ float g_ao  [Bn * Ln * Dm];
__device__ float g_lat [Bn * Ln * Dm];
__device__ float g_kvb [Bn * Ln * 2 * Dm];
__device__ float g_qb  [BEHn * Dm];

// ---------------- packed f32x2 helpers ----------------
__device__ __forceinline__ unsigned long long pk2(float lo, float hi) {
    unsigned long long r;
    asm("mov.b64 %0, {%1, %2};" : "=l"(r) : "f"(lo), "f"(hi));
    return r;
}
__device__ __forceinline__ void upk2(unsigned long long v, float& lo, float& hi) {
    asm("mov.b64 {%0, %1}, %2;" : "=f"(lo), "=f"(hi) : "l"(v));
}
__device__ __forceinline__ void fma2(unsigned long long& d, unsigned long long a, unsigned long long b) {
    asm("fma.rn.f32x2 %0, %1, %2, %0;" : "+l"(d) : "l"(a), "l"(b));
}

// ---------------- deterministic bucketing by batch ----------------
__global__ void hist_pass1(const int* __restrict__ bidx, int E) {
    int t = blockIdx.x * blockDim.x + threadIdx.x;
    int ch = (E + NTH - 1) / NTH;
    int s = t * ch, e = min(E, s + ch);
    int loc[Bn];
#pragma unroll
    for (int b = 0; b < Bn; b++) loc[b] = 0;
    for (int i = s; i < e; i++) loc[bidx[i] & (Bn - 1)]++;
#pragma unroll
    for (int b = 0; b < Bn; b++) g_hist[t * Bn + b] = loc[b];
}

__global__ void hist_scan() {
    __shared__ int tot[Bn], off[Bn];
    int b = threadIdx.x;
    if (b < Bn) {
        int run = 0;
        for (int t = 0; t < NTH; t++) {
            int v = g_hist[t * Bn + b];
            g_hist[t * Bn + b] = run;
            run += v;
        }
        tot[b] = run;
    }
    __syncthreads();
    if (threadIdx.x == 0) {
        int run = 0;
        for (int bb = 0; bb < Bn; bb++) { off[bb] = run; run += tot[bb]; }
    }
    __syncthreads();
    if (b < Bn) {
        g_cnt[b] = tot[b];
        g_off[b] = off[b];
        for (int t = 0; t < NTH; t++) g_hist[t * Bn + b] += off[b];
    }
}

__global__ void scatter_pass(const int* __restrict__ bidx, int E) {
    int t = blockIdx.x * blockDim.x + threadIdx.x;
    int ch = (E + NTH - 1) / NTH;
    int s = t * ch, e = min(E, s + ch);
    int base[Bn];
#pragma unroll
    for (int b = 0; b < Bn; b++) base[b] = g_hist[t * Bn + b];
    for (int i = s; i < e; i++) {
        int b = bidx[i] & (Bn - 1);
        g_order[base[b]++] = i;
    }
}

// ---------------- per-event LN stats (mu, rstd) from raw embeddings ----------------
__global__ void mustd_kernel(const int* __restrict__ nid, const int* __restrict__ tb,
                             const int* __restrict__ vv,
                             const float* __restrict__ ne, const float* __restrict__ te,
                             const float* __restrict__ ve, int E) {
    int w = (blockIdx.x * blockDim.x + threadIdx.x) >> 5;
    int lane = threadIdx.x & 31;
    if (w >= E) return;
    const float* pn = ne + (size_t)nid[w] * Dm;
    const float* pt = te + (size_t)tb[w] * Dm;
    const float* pv = ve + (size_t)vv[w] * Dm;
    float sum = 0.f, sq = 0.f;
#pragma unroll
    for (int i = 0; i < 8; i++) {
        int c = lane + i * 32;
        float v = pn[c] + pt[c] + pv[c];
        sum += v; sq += v * v;
    }
#pragma unroll
    for (int o = 16; o > 0; o >>= 1) {
        sum += __shfl_xor_sync(~0u, sum, o);
        sq  += __shfl_xor_sync(~0u, sq,  o);
    }
    float mean = sum * (1.f / Dm);
    float var = sq * (1.f / Dm) - mean * mean;
    if (lane == 0) {
        g_mu[w] = mean;
        g_rs[w] = rsqrtf(var + 1e-5f);
    }
}

// ---------------- column sums of Wkv ----------------
__global__ void csum_kernel(const float* __restrict__ Wkv) {
    int x = threadIdx.x;  // 512
    float s = 0.f;
    for (int k = 0; k < Dm; k++) s += Wkv[(size_t)k * 512 + x];
    g_csum[x] = s;
}

// ---------------- LN over 256 (warp per row) ----------------
__global__ void ln_kernel(const float* __restrict__ src, float* __restrict__ dst,
                          const float* __restrict__ w, const float* __restrict__ bb, int rows) {
    int r = (blockIdx.x * blockDim.x + threadIdx.x) >> 5;
    int lane = threadIdx.x & 31;
    if (r >= rows) return;
    const float* s = src + (size_t)r * Dm;
    float v[8]; float sum = 0.f, sq = 0.f;
#pragma unroll
    for (int i = 0; i < 8; i++) {
        v[i] = s[lane + i * 32];
        sum += v[i]; sq += v[i] * v[i];
    }
#pragma unroll
    for (int o = 16; o > 0; o >>= 1) {
        sum += __shfl_xor_sync(~0u, sum, o);
        sq  += __shfl_xor_sync(~0u, sq,  o);
    }
    float mean = sum * (1.f / Dm);
    float var = sq * (1.f / Dm) - mean * mean;
    float rs = rsqrtf(var + 1e-5f);
    float* d = dst + (size_t)r * Dm;
#pragma unroll
    for (int i = 0; i < 8; i++) {
        int c = lane + i * 32;
        float y = (v[i] - mean) * rs;
        if (w) y = y * w[c] + bb[c];
        d[c] = y;
    }
}

// ---------------- generic fp32 GEMM: C = op(A@B [+res]) ----------------
__global__ __launch_bounds__(256) void gemm_kernel(
    const float* __restrict__ A, const float* __restrict__ B,
    const float* __restrict__ res, float* __restrict__ C,
    int M, int N, int K, int mode) {
    __shared__ float As[16][128];
    __shared__ float Bs[16][64];
    int bm = blockIdx.x * 128, bn = blockIdx.y * 64;
    int t = threadIdx.x;
    int ty = t >> 4, tx = t & 15;
    float acc[8][4];
#pragma unroll
    for (int i = 0; i < 8; i++)
#pragma unroll
        for (int j = 0; j < 4; j++) acc[i][j] = 0.f;

    for (int k0 = 0; k0 < K; k0 += 16) {
#pragma unroll
        for (int i = 0; i < 8; i++) {
            int idx = t + i * 256;
            int m = idx >> 4, k = idx & 15;
            int gm = bm + m;
            As[k][m] = (gm < M) ? A[(size_t)gm * K + k0 + k] : 0.f;
        }
#pragma unroll
        for (int i = 0; i < 4; i++) {
            int idx = t + i * 256;
            int k = idx >> 6, n = idx & 63;
            Bs[k][n] = B[(size_t)(k0 + k) * N + bn + n];
        }
        __syncthreads();
#pragma unroll
        for (int kk = 0; kk < 16; kk++) {
            float a[8], b4[4];
#pragma unroll
            for (int i = 0; i < 8; i++) a[i] = As[kk][ty * 8 + i];
#pragma unroll
            for (int j = 0; j < 4; j++) b4[j] = Bs[kk][tx * 4 + j];
#pragma unroll
            for (int i = 0; i < 8; i++)
#pragma unroll
                for (int j = 0; j < 4; j++) acc[i][j] = fmaf(a[i], b4[j], acc[i][j]);
        }
        __syncthreads();
    }
#pragma unroll
    for (int i = 0; i < 8; i++) {
        int gm = bm + ty * 8 + i;
        if (gm >= M) continue;
#pragma unroll
        for (int j = 0; j < 4; j++) {
            int gn = bn + tx * 4 + j;
            float v = acc[i][j];
            if (mode == 1) v += res[(size_t)gm * N + gn];
            else if (mode == 2) {
                float x = v;
                v = 0.5f * x * (1.f + tanhf(0.7978845608028654f * (x + 0.044715f * x * x * x)));
            }
            C[(size_t)gm * N + gn] = v;
        }
    }
}

// ---------------- cross-attention: fused KV assembly + chunk partials ----------------
// grid (Bn, NCHUNK), 512 threads; thread = (h,l) pair
__global__ __launch_bounds__(512) void xattn_kernel(const int* __restrict__ nid,
                                                    const int* __restrict__ tb,
                                                    const int* __restrict__ vv) {
    int b = blockIdx.x, c = blockIdx.y;
    int cnt = min(g_cnt[b], EMAXC);
    int start = g_off[b] + c * CHUNKE;
    int n = cnt - c * CHUNKE;
    if (n > CHUNKE) n = CHUNKE;
    if (n < 0) n = 0;

    int t = threadIdx.x;
    int h = t >> 6, l = t & 63;

    __shared__ float4 skv4[8 * 128];   // 8 events x 512 floats
    __shared__ float4 scs4[128];       // csum (512 floats)
    float* skv = (float*)skv4;

    if (t < 128) scs4[t] = ((const float4*)g_csum)[t];

    // q packed as f32x2
    unsigned long long q2[16];
    {
        const float* qp = g_q + l * Dm + h * DHn;
#pragma unroll
        for (int i = 0; i < 16; i++) q2[i] = pk2(qp[2 * i], qp[2 * i + 1]);
    }
    unsigned long long vacc2[16];
#pragma unroll
    for (int i = 0; i < 16; i++) vacc2[i] = 0ULL;
    float se = 0.f;
    __syncthreads();

    const float4* NKV4 = (const float4*)g_nkv;
    const float4* TKV4 = (const float4*)g_tkv;
    const float4* VKV4 = (const float4*)g_vkv;

    for (int tile = 0; tile < n; tile += 8) {
        int ntile = n - tile; if (ntile > 8) ntile = 8;
        // assemble 8 events' K|V from projected embedding tables (L2-resident)
#pragma unroll
        for (int pass = 0; pass < 2; pass++) {
            int idx = t + pass * 512;
            int e = idx >> 7, x = idx & 127;     // x: float4 index within 512 floats
            float4 r = make_float4(0.f, 0.f, 0.f, 0.f);
            if (e < ntile) {
                int o = g_order[start + tile + e];
                float mu = g_mu[o], rs = g_rs[o];
                float4 a = NKV4[(size_t)nid[o] * 128 + x];
                float4 bb = TKV4[(size_t)tb[o]  * 128 + x];
                float4 cc = VKV4[(size_t)vv[o]  * 128 + x];
                float4 cs = scs4[x];
                r.x = (a.x + bb.x + cc.x - mu * cs.x) * rs;
                r.y = (a.y + bb.y + cc.y - mu * cs.y) * rs;
                r.z = (a.z + bb.z + cc.z - mu * cs.z) * rs;
                r.w = (a.w + bb.w + cc.w - mu * cs.w) * rs;
            }
            skv4[idx] = r;
        }
        __syncthreads();
        for (int e = 0; e < ntile; e++) {
            const float4* kk4 = (const float4*)(skv + e * 512 + h * DHn);
            const float4* vv4 = kk4 + 64;   // +256 floats
            unsigned long long sa = 0ULL;
#pragma unroll
            for (int i = 0; i < 8; i++) {
                float4 k = kk4[i];
                fma2(sa, q2[2 * i],     pk2(k.x, k.y));
                fma2(sa, q2[2 * i + 1], pk2(k.z, k.w));
            }
            float slo, shi; upk2(sa, slo, shi);
            float w = __expf((slo + shi) * SCALE);
            se += w;
            unsigned long long w2 = pk2(w, w);
#pragma unroll
            for (int i = 0; i < 8; i++) {
                float4 v = vv4[i];
                fma2(vacc2[2 * i],     w2, pk2(v.x, v.y));
                fma2(vacc2[2 * i + 1], w2, pk2(v.z, v.w));
            }
        }
        __syncthreads();
    }
    size_t base = (size_t)(b * NCHUNK + c) * 512 + t;
    g_psum[base] = se;
    float* pv = g_pv + base * 32;
#pragma unroll
    for (int i = 0; i < 16; i++) {
        float lo, hi; upk2(vacc2[i], lo, hi);
        pv[2 * i] = lo; pv[2 * i + 1] = hi;
    }
}

// deterministic reduce over chunks; warp per (b, h, l)
__global__ void xreduce_kernel() {
    int g = blockIdx.x * 8 + (threadIdx.x >> 5);
    int lane = threadIdx.x & 31;
    int b = g >> 9, p = g & 511;
    float vs = 0.f, ss = 0.f;
    for (int c = 0; c < NCHUNK; c++) {
        size_t base = (size_t)(b * NCHUNK + c) * 512 + p;
        ss += g_psum[base];
        vs += g_pv[base * 32 + lane];
    }
    float o = vs / ss;
    int h = p >> 6, l = p & 63;
    g_ao[(size_t)(b * Ln + l) * Dm + h * DHn + lane] = o;
}

__global__ void bcast_lat(const float* __restrict__ lat_init) {
    int i = blockIdx.x * blockDim.x + threadIdx.x;
    if (i < Bn * Ln * Dm) g_lat[i] = lat_init[i & (Ln * Dm - 1)];
}

// ---------------- self-attention (64 latents), grid (Bn*Hn), 64 threads ----------------
__global__ __launch_bounds__(64) void selfattn_kernel() {
    int b = blockIdx.x >> 3, h = blockIdx.x & 7;
    __shared__ float ks[Ln * DHn], vs_[Ln * DHn], sc[Ln * Ln];
    int t = threadIdx.x;  // = query index l
    const float* rowq = g_qkv + (size_t)(b * Ln + t) * (3 * Dm);
    float q[32];
#pragma unroll
    for (int d = 0; d < 32; d++) {
        q[d] = rowq[h * DHn + d];
        ks[t * DHn + d]  = rowq[Dm + h * DHn + d];
        vs_[t * DHn + d] = rowq[2 * Dm + h * DHn + d];
    }
    __syncthreads();
    float m = -1e30f;
    for (int j = 0; j < Ln; j++) {
        float s = 0.f;
#pragma unroll
        for (int d = 0; d < 32; d++) s = fmaf(q[d], ks[j * DHn + d], s);
        s *= SCALE;
        sc[t * Ln + j] = s;
        m = fmaxf(m, s);
    }
    float sum = 0.f;
    for (int j = 0; j < Ln; j++) {
        float w = __expf(sc[t * Ln + j] - m);
        sc[t * Ln + j] = w;
        sum += w;
    }
    float inv = 1.f / sum;
    float o[32];
#pragma unroll
    for (int d = 0; d < 32; d++) o[d] = 0.f;
    for (int j = 0; j < Ln; j++) {
        float w = sc[t * Ln + j];
#pragma unroll
        for (int d = 0; d < 32; d++) o[d] = fmaf(w, vs_[j * DHn + d], o[d]);
    }
    float* dst = g_ao + (size_t)(b * Ln + t) * Dm + h * DHn;
#pragma unroll
    for (int d = 0; d < 32; d++) dst[d] = o[d] * inv;
}

// ---------------- behavior decoder attention + projection ----------------
__global__ __launch_bounds__(64) void bh_kernel(const float* __restrict__ wo, float* __restrict__ out) {
    int b = blockIdx.x, t = threadIdx.x;
    __shared__ float part[16];
    if (t < 16) {
        int qi = t >> 3, h = t & 7;
        float q[32];
#pragma unroll
        for (int d = 0; d < 32; d++) q[d] = g_qb[qi * Dm + h * DHn + d];
        float s[Ln];
        float m = -1e30f;
        for (int j = 0; j < Ln; j++) {
            const float* kp = g_kvb + (size_t)(b * Ln + j) * (2 * Dm) + h * DHn;
            float acc = 0.f;
#pragma unroll
            for (int d = 0; d < 32; d++) acc = fmaf(q[d], kp[d], acc);
            acc *= SCALE;
            s[j] = acc;
            m = fmaxf(m, acc);
        }
        float sum = 0.f;
        for (int j = 0; j < Ln; j++) { s[j] = __expf(s[j] - m); sum += s[j]; }
        float o[32];
#pragma unroll
        for (int d = 0; d < 32; d++) o[d] = 0.f;
        for (int j = 0; j < Ln; j++) {
            const float* vp = g_kvb + (size_t)(b * Ln + j) * (2 * Dm) + Dm + h * DHn;
            float w = s[j];
#pragma unroll
            for (int d = 0; d < 32; d++) o[d] = fmaf(w, vp[d], o[d]);
        }
        float inv = 1.f / sum;
        float partial = 0.f;
#pragma unroll
        for (int d = 0; d < 32; d++) partial += o[d] * inv * wo[h * DHn + d];
        part[t] = partial;
    }
    __syncthreads();
    if (t < BEHn) {
        float r = 0.f;
        for (int h = 0; h < Hn; h++) r += part[t * 8 + h];
        out[b * BEHn + t] = r;
    }
}

// ---------------- spike head: mean over L, then 256x64 ----------------
__global__ void spike_kernel(const float* __restrict__ spw, const float* __restrict__ spb,
                             float* __restrict__ out) {
    int b = blockIdx.x, t = threadIdx.x;
    __shared__ float mean[Dm];
    float acc = 0.f;
    for (int l = 0; l < Ln; l++) acc += g_lat[(size_t)(b * Ln + l) * Dm + t];
    mean[t] = acc * (1.f / Ln);
    __syncthreads();
    if (t < SPKn) {
        float r = spb[t];
        for (int d = 0; d < Dm; d++) r = fmaf(mean[d], spw[d * SPKn + t], r);
        out[Bn * BEHn + b * SPKn + t] = r;
    }
}

// ---------------- host ----------------
static inline void gemm(const float* A, const float* B, const float* res, float* C,
                        int M, int N, int K, int mode) {
    dim3 g((M + 127) / 128, N / 64);
    gemm_kernel<<<g, 256>>>(A, B, res, C, M, N, K, mode);
}

extern "C" void kernel_launch(void* const* d_in, const int* in_sizes, int n_in,
                              void* d_out, int out_size) {
    int map[27];
    if (in_sizes[0] < 1000000) {
        for (int i = 0; i < 27; i++) map[i] = i;  // dict order
    } else {
        int m2[27] = {21,22,23,24,25,26, 0,1,2,3,4,5,6,7,8,9,10,11,12,13,14,15,16,17,18,19,20};
        for (int i = 0; i < 27; i++) map[i] = m2[i];
    }
    const int*   nid  = (const int*)  d_in[map[0]];
    const int*   tbv  = (const int*)  d_in[map[1]];
    const int*   vals = (const int*)  d_in[map[2]];
    const int*   bidx = (const int*)  d_in[map[3]];
    const float* ne   = (const float*)d_in[map[6]];
    const float* te   = (const float*)d_in[map[7]];
    const float* ve   = (const float*)d_in[map[8]];
    const float* lat0 = (const float*)d_in[map[9]];
    const float* Wq   = (const float*)d_in[map[10]];
    const float* Wkv  = (const float*)d_in[map[11]];
    const float* Wo   = (const float*)d_in[map[12]];
    const float* W1   = (const float*)d_in[map[13]];
    const float* W2   = (const float*)d_in[map[14]];
    const float* Wqkv_s = (const float*)d_in[map[15]];
    const float* Wo_s   = (const float*)d_in[map[16]];
    const float* W1_s   = (const float*)d_in[map[17]];
    const float* W2_s   = (const float*)d_in[map[18]];
    const float* bhq    = (const float*)d_in[map[19]];
    const float* bhwq   = (const float*)d_in[map[20]];
    const float* bhwkv  = (const float*)d_in[map[21]];
    const float* bhwo   = (const float*)d_in[map[22]];
    const float* lnw    = (const float*)d_in[map[23]];
    const float* lnb    = (const float*)d_in[map[24]];
    const float* spw    = (const float*)d_in[map[25]];
    const float* spb    = (const float*)d_in[map[26]];
    int E = in_sizes[map[0]];
    if (E > EMAXE) E = EMAXE;
    float* out = (float*)d_out;

    void *p_nkv, *p_tkv, *p_vkv, *p_q, *p_x, *p_qkv, *p_h, *p_ao, *p_lat, *p_kvb, *p_qb;
    cudaGetSymbolAddress(&p_nkv, g_nkv);
    cudaGetSymbolAddress(&p_tkv, g_tkv);
    cudaGetSymbolAddress(&p_vkv, g_vkv);
    cudaGetSymbolAddress(&p_q,   g_q);
    cudaGetSymbolAddress(&p_x,   g_x);
    cudaGetSymbolAddress(&p_qkv, g_qkv);
    cudaGetSymbolAddress(&p_h,   g_hbuf);
    cudaGetSymbolAddress(&p_ao,  g_ao);
    cudaGetSymbolAddress(&p_lat, g_lat);
    cudaGetSymbolAddress(&p_kvb, g_kvb);
    cudaGetSymbolAddress(&p_qb,  g_qb);
    float* f_nkv = (float*)p_nkv; float* f_tkv = (float*)p_tkv; float* f_vkv = (float*)p_vkv;
    float* f_q = (float*)p_q; float* f_x = (float*)p_x; float* f_qkv = (float*)p_qkv;
    float* f_h = (float*)p_h; float* f_ao = (float*)p_ao; float* f_lat = (float*)p_lat;
    float* f_kvb = (float*)p_kvb; float* f_qb = (float*)p_qb;

    // 1) deterministic bucket-by-batch
    hist_pass1<<<NTH / 256, 256>>>(bidx, E);
    hist_scan<<<1, 32>>>();
    scatter_pass<<<NTH / 256, 256>>>(bidx, E);

    // 2) per-event LN stats (mu, rstd)
    mustd_kernel<<<(E + 7) / 8, 256>>>(nid, tbv, vals, ne, te, ve, E);

    // 3) embedding-table KV projections (replaces the E x 512 x 256 GEMM)
    gemm(ne, Wkv, nullptr, f_nkv, NEURONSn, 2 * Dm, Dm, 0);
    gemm(te, Wkv, nullptr, f_tkv, TBINSn,   2 * Dm, Dm, 0);
    gemm(ve, Wkv, nullptr, f_vkv, VBUCKn,   2 * Dm, Dm, 0);
    csum_kernel<<<1, 512>>>(Wkv);

    // 4) Q (identical for all batches): LN(lat_init) @ Wq_c
    ln_kernel<<<8, 256>>>(lat0, f_x, nullptr, nullptr, Ln);
    gemm(f_x, Wq, nullptr, f_q, Ln, Dm, Dm, 0);

    // 5) cross-attention partials + deterministic reduce
    xattn_kernel<<<dim3(Bn, NCHUNK), 512>>>(nid, tbv, vals);
    xreduce_kernel<<<Bn * 512 / 8, 256>>>();

    // 6) residual stream
    bcast_lat<<<(Bn * Ln * Dm) / 256, 256>>>(lat0);
    gemm(f_ao, Wo, f_lat, f_lat, Bn * Ln, Dm, Dm, 1);

    // 7) cross-block MLP
    ln_kernel<<<(Bn * Ln) / 8, 256>>>(f_lat, f_x, nullptr, nullptr, Bn * Ln);
    gemm(f_x, W1, nullptr, f_h, Bn * Ln, 4 * Dm, Dm, 2);
    gemm(f_h, W2, f_lat, f_lat, Bn * Ln, Dm, 4 * Dm, 1);

    // 8) self-attention blocks
    for (int i = 0; i < NLn; i++) {
        ln_kernel<<<(Bn * Ln) / 8, 256>>>(f_lat, f_x, nullptr, nullptr, Bn * Ln);
        gemm(f_x, Wqkv_s + (size_t)i * Dm * 3 * Dm, nullptr, f_qkv, Bn * Ln, 3 * Dm, Dm, 0);
        selfattn_kernel<<<Bn * Hn, 64>>>();
        gemm(f_ao, Wo_s + (size_t)i * Dm * Dm, f_lat, f_lat, Bn * Ln, Dm, Dm, 1);
        ln_kernel<<<(Bn * Ln) / 8, 256>>>(f_lat, f_x, nullptr, nullptr, Bn * Ln);
        gemm(f_x, W1_s + (size_t)i * Dm * 4 * Dm, nullptr, f_h, Bn * Ln, 4 * Dm, Dm, 2);
        gemm(f_h, W2_s + (size_t)i * 4 * Dm * Dm, f_lat, f_lat, Bn * Ln, Dm, 4 * Dm, 1);
    }

    // 9) behavior decoder
    ln_kernel<<<(Bn * Ln) / 8, 256>>>(f_lat, f_x, lnw, lnb, Bn * Ln);
    gemm(f_x, bhwkv, nullptr, f_kvb, Bn * Ln, 2 * Dm, Dm, 0);
    gemm(bhq, bhwq, nullptr, f_qb, BEHn, Dm, Dm, 0);
    bh_kernel<<<Bn, 64>>>(bhwo, out);

    // 10) spike head
    spike_kernel<<<Bn, 256>>>(spw, spb, out);
}

// round 3
// speedup vs baseline: 2.1865x; 1.1393x over previous
#include <cuda_runtime.h>
#include <cuda_bf16.h>
#include <math.h>

// ---------------- model constants ----------------
#define Dm    256
#define Hn    8
#define DHn   32
#define Ln    64
#define BEHn  2
#define SPKn  64
#define NLn   2
#define Bn    16
#define NEURONSn 4096
#define TBINSn   1024
#define VBUCKn   256
#define EMAXC 13568          // max_events cap
#define CHUNKE 512           // events per cross-attn chunk
#define NCHUNK 27            // 27*512 = 13824 >= 13568
#define EMAXE 200000         // event buffer capacity
#define NTH   2048           // partitions for deterministic bucket scan

#define SCALE 0.17677669529663687f   // 1/sqrt(32)

// ---------------- scratch ----------------
__device__ float g_nkv[(size_t)NEURONSn * 2 * Dm];
__device__ float g_tkv[(size_t)TBINSn   * 2 * Dm];
__device__ float g_vkv[(size_t)VBUCKn   * 2 * Dm];
__device__ float g_csum[2 * Dm];
__device__ float g_mu[EMAXE];
__device__ float g_rs[EMAXE];
__device__ int   g_order[EMAXE];
__device__ int   g_hist[NTH * Bn];
__device__ int   g_cnt[Bn];
__device__ int   g_off[Bn];
__device__ float g_psum[Bn * NCHUNK * 512];
__device__ float g_pv [(size_t)Bn * NCHUNK * 512 * 32];
__device__ float g_q   [Ln * Dm];
__device__ float g_x   [Bn * Ln * Dm];
__device__ float g_qkv [Bn * Ln * 3 * Dm];
__device__ float g_hbuf[Bn * Ln * 4 * Dm];
__device__ float g_ao  [Bn * Ln * Dm];
__device__ float g_lat [Bn * Ln * Dm];
__device__ float g_kvb [Bn * Ln * 2 * Dm];
__device__ float g_qb  [BEHn * Dm];

// ---------------- packed f32x2 helpers ----------------
__device__ __forceinline__ unsigned long long pk2(float lo, float hi) {
    unsigned long long r;
    asm("mov.b64 %0, {%1, %2};" : "=l"(r) : "f"(lo), "f"(hi));
    return r;
}
__device__ __forceinline__ void upk2(unsigned long long v, float& lo, float& hi) {
    asm("mov.b64 {%0, %1}, %2;" : "=f"(lo), "=f"(hi) : "l"(v));
}
__device__ __forceinline__ void fma2(unsigned long long& d, unsigned long long a, unsigned long long b) {
    asm("fma.rn.f32x2 %0, %1, %2, %0;" : "+l"(d) : "l"(a), "l"(b));
}

// ---------------- deterministic bucketing by batch ----------------
__global__ void hist_pass1(const int* __restrict__ bidx, int E) {
    int t = blockIdx.x * blockDim.x + threadIdx.x;
    int ch = (E + NTH - 1) / NTH;
    int s = t * ch, e = min(E, s + ch);
    int loc[Bn];
#pragma unroll
    for (int b = 0; b < Bn; b++) loc[b] = 0;
    for (int i = s; i < e; i++) loc[bidx[i] & (Bn - 1)]++;
#pragma unroll
    for (int b = 0; b < Bn; b++) g_hist[t * Bn + b] = loc[b];
}

// parallel scan: warp w handles batch b=w over 2048 partials
__global__ void hist_scan(void) {
    __shared__ int tot[Bn], off[Bn];
    int w = threadIdx.x >> 5, lane = threadIdx.x & 31;
    int b = w;   // 16 warps
    int run = 0;
    for (int i = 0; i < NTH / 32; i++) {
        int idx = i * 32 + lane;
        int v = g_hist[idx * Bn + b];
        int incl = v;
#pragma unroll
        for (int o = 1; o < 32; o <<= 1) {
            int u = __shfl_up_sync(~0u, incl, o);
            if (lane >= o) incl += u;
        }
        g_hist[idx * Bn + b] = run + incl - v;
        run += __shfl_sync(~0u, incl, 31);
    }
    if (lane == 0) tot[b] = run;
    __syncthreads();
    if (threadIdx.x == 0) {
        int r = 0;
        for (int bb = 0; bb < Bn; bb++) { off[bb] = r; r += tot[bb]; }
    }
    __syncthreads();
    if (lane == 0) { g_cnt[b] = tot[b]; g_off[b] = off[b]; }
    int ob = off[b];
    for (int i = 0; i < NTH / 32; i++) {
        int idx = i * 32 + lane;
        g_hist[idx * Bn + b] += ob;
    }
}

__global__ void scatter_pass(const int* __restrict__ bidx, int E) {
    int t = blockIdx.x * blockDim.x + threadIdx.x;
    int ch = (E + NTH - 1) / NTH;
    int s = t * ch, e = min(E, s + ch);
    int base[Bn];
#pragma unroll
    for (int b = 0; b < Bn; b++) base[b] = g_hist[t * Bn + b];
    for (int i = s; i < e; i++) {
        int b = bidx[i] & (Bn - 1);
        g_order[base[b]++] = i;
    }
}

// ---------------- per-event LN stats ----------------
__global__ void mustd_kernel(const int* __restrict__ nid, const int* __restrict__ tb,
                             const int* __restrict__ vv,
                             const float* __restrict__ ne, const float* __restrict__ te,
                             const float* __restrict__ ve, int E) {
    int w = (blockIdx.x * blockDim.x + threadIdx.x) >> 5;
    int lane = threadIdx.x & 31;
    if (w >= E) return;
    const float* pn = ne + (size_t)nid[w] * Dm;
    const float* pt = te + (size_t)tb[w] * Dm;
    const float* pv = ve + (size_t)vv[w] * Dm;
    float sum = 0.f, sq = 0.f;
#pragma unroll
    for (int i = 0; i < 8; i++) {
        int c = lane + i * 32;
        float v = pn[c] + pt[c] + pv[c];
        sum += v; sq += v * v;
    }
#pragma unroll
    for (int o = 16; o > 0; o >>= 1) {
        sum += __shfl_xor_sync(~0u, sum, o);
        sq  += __shfl_xor_sync(~0u, sq,  o);
    }
    float mean = sum * (1.f / Dm);
    float var = sq * (1.f / Dm) - mean * mean;
    if (lane == 0) {
        g_mu[w] = mean;
        g_rs[w] = rsqrtf(var + 1e-5f);
    }
}

__global__ void csum_kernel(const float* __restrict__ Wkv) {
    int x = threadIdx.x;  // 512
    float s = 0.f;
    for (int k = 0; k < Dm; k++) s += Wkv[(size_t)k * 512 + x];
    g_csum[x] = s;
}

// ---------------- LN over 256 (warp per row) ----------------
__global__ void ln_kernel(const float* __restrict__ src, float* __restrict__ dst,
                          const float* __restrict__ w, const float* __restrict__ bb, int rows) {
    int r = (blockIdx.x * blockDim.x + threadIdx.x) >> 5;
    int lane = threadIdx.x & 31;
    if (r >= rows) return;
    const float* s = src + (size_t)r * Dm;
    float v[8]; float sum = 0.f, sq = 0.f;
#pragma unroll
    for (int i = 0; i < 8; i++) {
        v[i] = s[lane + i * 32];
        sum += v[i]; sq += v[i] * v[i];
    }
#pragma unroll
    for (int o = 16; o > 0; o >>= 1) {
        sum += __shfl_xor_sync(~0u, sum, o);
        sq  += __shfl_xor_sync(~0u, sq,  o);
    }
    float mean = sum * (1.f / Dm);
    float var = sq * (1.f / Dm) - mean * mean;
    float rs = rsqrtf(var + 1e-5f);
    float* d = dst + (size_t)r * Dm;
#pragma unroll
    for (int i = 0; i < 8; i++) {
        int c = lane + i * 32;
        float y = (v[i] - mean) * rs;
        if (w) y = y * w[c] + bb[c];
        d[c] = y;
    }
}

// ---------------- fp32 GEMM, 128x64 tile ----------------
__global__ __launch_bounds__(256) void gemm_kernel(
    const float* __restrict__ A, const float* __restrict__ B,
    const float* __restrict__ res, float* __restrict__ C,
    int M, int N, int K, int mode) {
    __shared__ float As[16][128];
    __shared__ float Bs[16][64];
    int bm = blockIdx.x * 128, bn = blockIdx.y * 64;
    int t = threadIdx.x;
    int ty = t >> 4, tx = t & 15;
    float acc[8][4];
#pragma unroll
    for (int i = 0; i < 8; i++)
#pragma unroll
        for (int j = 0; j < 4; j++) acc[i][j] = 0.f;

    for (int k0 = 0; k0 < K; k0 += 16) {
#pragma unroll
        for (int i = 0; i < 8; i++) {
            int idx = t + i * 256;
            int m = idx >> 4, k = idx & 15;
            int gm = bm + m;
            As[k][m] = (gm < M) ? A[(size_t)gm * K + k0 + k] : 0.f;
        }
#pragma unroll
        for (int i = 0; i < 4; i++) {
            int idx = t + i * 256;
            int k = idx >> 6, n = idx & 63;
            Bs[k][n] = B[(size_t)(k0 + k) * N + bn + n];
        }
        __syncthreads();
#pragma unroll
        for (int kk = 0; kk < 16; kk++) {
            float a[8], b4[4];
#pragma unroll
            for (int i = 0; i < 8; i++) a[i] = As[kk][ty * 8 + i];
#pragma unroll
            for (int j = 0; j < 4; j++) b4[j] = Bs[kk][tx * 4 + j];
#pragma unroll
            for (int i = 0; i < 8; i++)
#pragma unroll
                for (int j = 0; j < 4; j++) acc[i][j] = fmaf(a[i], b4[j], acc[i][j]);
        }
        __syncthreads();
    }
#pragma unroll
    for (int i = 0; i < 8; i++) {
        int gm = bm + ty * 8 + i;
        if (gm >= M) continue;
#pragma unroll
        for (int j = 0; j < 4; j++) {
            int gn = bn + tx * 4 + j;
            float v = acc[i][j];
            if (mode == 1) v += res[(size_t)gm * N + gn];
            else if (mode == 2) {
                float x = v;
                v = 0.5f * x * (1.f + tanhf(0.7978845608028654f * (x + 0.044715f * x * x * x)));
            }
            C[(size_t)gm * N + gn] = v;
        }
    }
}

// ---------------- fp32 GEMM, 32x64 tile (skinny-M utilization) ----------------
__global__ __launch_bounds__(256) void gemm_kernel32(
    const float* __restrict__ A, const float* __restrict__ B,
    const float* __restrict__ res, float* __restrict__ C,
    int M, int N, int K, int mode) {
    __shared__ float As[16][32];
    __shared__ float Bs[16][64];
    int bm = blockIdx.x * 32, bn = blockIdx.y * 64;
    int t = threadIdx.x;
    int ty = t >> 4, tx = t & 15;  // ty: 0..15 -> 2 rows each, tx: 4 cols each
    float acc[2][4];
#pragma unroll
    for (int i = 0; i < 2; i++)
#pragma unroll
        for (int j = 0; j < 4; j++) acc[i][j] = 0.f;

    for (int k0 = 0; k0 < K; k0 += 16) {
#pragma unroll
        for (int i = 0; i < 2; i++) {
            int idx = t + i * 256;
            int m = idx >> 4, k = idx & 15;
            int gm = bm + m;
            As[k][m] = (gm < M) ? A[(size_t)gm * K + k0 + k] : 0.f;
        }
#pragma unroll
        for (int i = 0; i < 4; i++) {
            int idx = t + i * 256;
            int k = idx >> 6, n = idx & 63;
            Bs[k][n] = B[(size_t)(k0 + k) * N + bn + n];
        }
        __syncthreads();
#pragma unroll
        for (int kk = 0; kk < 16; kk++) {
            float a0 = As[kk][ty * 2], a1 = As[kk][ty * 2 + 1];
            float b4[4];
#pragma unroll
            for (int j = 0; j < 4; j++) b4[j] = Bs[kk][tx * 4 + j];
#pragma unroll
            for (int j = 0; j < 4; j++) {
                acc[0][j] = fmaf(a0, b4[j], acc[0][j]);
                acc[1][j] = fmaf(a1, b4[j], acc[1][j]);
            }
        }
        __syncthreads();
    }
#pragma unroll
    for (int i = 0; i < 2; i++) {
        int gm = bm + ty * 2 + i;
        if (gm >= M) continue;
#pragma unroll
        for (int j = 0; j < 4; j++) {
            int gn = bn + tx * 4 + j;
            float v = acc[i][j];
            if (mode == 1) v += res[(size_t)gm * N + gn];
            else if (mode == 2) {
                float x = v;
                v = 0.5f * x * (1.f + tanhf(0.7978845608028654f * (x + 0.044715f * x * x * x)));
            }
            C[(size_t)gm * N + gn] = v;
        }
    }
}

// ---------------- cross-attention: fused KV assembly + chunk partials ----------------
// grid (Bn, NCHUNK), 256 threads; thread = (h, l) and (h, l+32)
__global__ __launch_bounds__(256) void xattn_kernel(const int* __restrict__ nid,
                                                    const int* __restrict__ tb,
                                                    const int* __restrict__ vv) {
    int b = blockIdx.x, c = blockIdx.y;
    int cnt = min(g_cnt[b], EMAXC);
    int start = g_off[b] + c * CHUNKE;
    int n = cnt - c * CHUNKE;
    if (n > CHUNKE) n = CHUNKE;
    if (n < 0) n = 0;

    int t = threadIdx.x;
    int h = t >> 5, li = t & 31;   // latents li and li+32, head h (warp-uniform)

    __shared__ float4 skv4[8 * 128];   // 8 events x 512 floats
    __shared__ float4 scs4[128];
    float* skv = (float*)skv4;

    if (t < 128) scs4[t] = ((const float4*)g_csum)[t];

    unsigned long long qa[16], qb[16];
    {
        const float* qp0 = g_q + li * Dm + h * DHn;
        const float* qp1 = g_q + (li + 32) * Dm + h * DHn;
#pragma unroll
        for (int i = 0; i < 16; i++) {
            qa[i] = pk2(qp0[2 * i], qp0[2 * i + 1]);
            qb[i] = pk2(qp1[2 * i], qp1[2 * i + 1]);
        }
    }
    unsigned long long va[16], vb[16];
#pragma unroll
    for (int i = 0; i < 16; i++) { va[i] = 0ULL; vb[i] = 0ULL; }
    float sea = 0.f, seb = 0.f;
    __syncthreads();

    const float4* NKV4 = (const float4*)g_nkv;
    const float4* TKV4 = (const float4*)g_tkv;
    const float4* VKV4 = (const float4*)g_vkv;

    for (int tile = 0; tile < n; tile += 8) {
        int ntile = n - tile; if (ntile > 8) ntile = 8;
#pragma unroll
        for (int pass = 0; pass < 4; pass++) {
            int idx = t + pass * 256;
            int e = idx >> 7, x = idx & 127;
            float4 r = make_float4(0.f, 0.f, 0.f, 0.f);
            if (e < ntile) {
                int o = g_order[start + tile + e];
                float mu = g_mu[o], rs = g_rs[o];
                float4 a = NKV4[(size_t)nid[o] * 128 + x];
                float4 bb = TKV4[(size_t)tb[o]  * 128 + x];
                float4 cc = VKV4[(size_t)vv[o]  * 128 + x];
                float4 cs = scs4[x];
                r.x = (a.x + bb.x + cc.x - mu * cs.x) * rs;
                r.y = (a.y + bb.y + cc.y - mu * cs.y) * rs;
                r.z = (a.z + bb.z + cc.z - mu * cs.z) * rs;
                r.w = (a.w + bb.w + cc.w - mu * cs.w) * rs;
            }
            skv4[idx] = r;
        }
        __syncthreads();
        for (int e = 0; e < ntile; e++) {
            const float4* kk4 = (const float4*)(skv + e * 512 + h * DHn);
            const float4* vv4 = kk4 + 64;
            unsigned long long sa0 = 0ULL, sa1 = 0ULL, sb0 = 0ULL, sb1 = 0ULL;
#pragma unroll
            for (int i = 0; i < 4; i++) {
                float4 k0 = kk4[2 * i], k1 = kk4[2 * i + 1];
                unsigned long long klo0 = pk2(k0.x, k0.y), khi0 = pk2(k0.z, k0.w);
                unsigned long long klo1 = pk2(k1.x, k1.y), khi1 = pk2(k1.z, k1.w);
                fma2(sa0, qa[4 * i],     klo0);
                fma2(sa1, qa[4 * i + 1], khi0);
                fma2(sa0, qa[4 * i + 2], klo1);
                fma2(sa1, qa[4 * i + 3], khi1);
                fma2(sb0, qb[4 * i],     klo0);
                fma2(sb1, qb[4 * i + 1], khi0);
                fma2(sb0, qb[4 * i + 2], klo1);
                fma2(sb1, qb[4 * i + 3], khi1);
            }
            float x0, x1, y0, y1;
            upk2(sa0, x0, x1); float da = x0 + x1;
            upk2(sa1, y0, y1); da += y0 + y1;
            upk2(sb0, x0, x1); float db = x0 + x1;
            upk2(sb1, y0, y1); db += y0 + y1;
            float wa = __expf(da * SCALE);
            float wb = __expf(db * SCALE);
            sea += wa; seb += wb;
            unsigned long long wa2 = pk2(wa, wa), wb2 = pk2(wb, wb);
#pragma unroll
            for (int i = 0; i < 8; i++) {
                float4 v = vv4[i];
                unsigned long long vlo = pk2(v.x, v.y), vhi = pk2(v.z, v.w);
                fma2(va[2 * i],     wa2, vlo);
                fma2(va[2 * i + 1], wa2, vhi);
                fma2(vb[2 * i],     wb2, vlo);
                fma2(vb[2 * i + 1], wb2, vhi);
            }
        }
        __syncthreads();
    }
    int p0 = h * 64 + li, p1 = p0 + 32;
    size_t base0 = (size_t)(b * NCHUNK + c) * 512 + p0;
    size_t base1 = (size_t)(b * NCHUNK + c) * 512 + p1;
    g_psum[base0] = sea;
    g_psum[base1] = seb;
    float* pv0 = g_pv + base0 * 32;
    float* pv1 = g_pv + base1 * 32;
#pragma unroll
    for (int i = 0; i < 16; i++) {
        float lo, hi;
        upk2(va[i], lo, hi); pv0[2 * i] = lo; pv0[2 * i + 1] = hi;
        upk2(vb[i], lo, hi); pv1[2 * i] = lo; pv1[2 * i + 1] = hi;
    }
}

// deterministic reduce over chunks; warp per (b, h, l)
__global__ void xreduce_kernel() {
    int g = blockIdx.x * 8 + (threadIdx.x >> 5);
    int lane = threadIdx.x & 31;
    int b = g >> 9, p = g & 511;
    float vs = 0.f, ss = 0.f;
    for (int c = 0; c < NCHUNK; c++) {
        size_t base = (size_t)(b * NCHUNK + c) * 512 + p;
        ss += g_psum[base];
        vs += g_pv[base * 32 + lane];
    }
    float o = vs / ss;
    int h = p >> 6, l = p & 63;
    g_ao[(size_t)(b * Ln + l) * Dm + h * DHn + lane] = o;
}

__global__ void bcast_lat(const float* __restrict__ lat_init) {
    int i = blockIdx.x * blockDim.x + threadIdx.x;
    if (i < Bn * Ln * Dm) g_lat[i] = lat_init[i & (Ln * Dm - 1)];
}

// ---------------- self-attention ----------------
__global__ __launch_bounds__(64) void selfattn_kernel() {
    int b = blockIdx.x >> 3, h = blockIdx.x & 7;
    __shared__ float ks[Ln * DHn], vs_[Ln * DHn], sc[Ln * Ln];
    int t = threadIdx.x;
    const float* rowq = g_qkv + (size_t)(b * Ln + t) * (3 * Dm);
    float q[32];
#pragma unroll
    for (int d = 0; d < 32; d++) {
        q[d] = rowq[h * DHn + d];
        ks[t * DHn + d]  = rowq[Dm + h * DHn + d];
        vs_[t * DHn + d] = rowq[2 * Dm + h * DHn + d];
    }
    __syncthreads();
    float m = -1e30f;
    for (int j = 0; j < Ln; j++) {
        float s = 0.f;
#pragma unroll
        for (int d = 0; d < 32; d++) s = fmaf(q[d], ks[j * DHn + d], s);
        s *= SCALE;
        sc[t * Ln + j] = s;
        m = fmaxf(m, s);
    }
    float sum = 0.f;
    for (int j = 0; j < Ln; j++) {
        float w = __expf(sc[t * Ln + j] - m);
        sc[t * Ln + j] = w;
        sum += w;
    }
    float inv = 1.f / sum;
    float o[32];
#pragma unroll
    for (int d = 0; d < 32; d++) o[d] = 0.f;
    for (int j = 0; j < Ln; j++) {
        float w = sc[t * Ln + j];
#pragma unroll
        for (int d = 0; d < 32; d++) o[d] = fmaf(w, vs_[j * DHn + d], o[d]);
    }
    float* dst = g_ao + (size_t)(b * Ln + t) * Dm + h * DHn;
#pragma unroll
    for (int d = 0; d < 32; d++) dst[d] = o[d] * inv;
}

// ---------------- behavior decoder ----------------
__global__ __launch_bounds__(64) void bh_kernel(const float* __restrict__ wo, float* __restrict__ out) {
    int b = blockIdx.x, t = threadIdx.x;
    __shared__ float part[16];
    if (t < 16) {
        int qi = t >> 3, h = t & 7;
        float q[32];
#pragma unroll
        for (int d = 0; d < 32; d++) q[d] = g_qb[qi * Dm + h * DHn + d];
        float s[Ln];
        float m = -1e30f;
        for (int j = 0; j < Ln; j++) {
            const float* kp = g_kvb + (size_t)(b * Ln + j) * (2 * Dm) + h * DHn;
            float acc = 0.f;
#pragma unroll
            for (int d = 0; d < 32; d++) acc = fmaf(q[d], kp[d], acc);
            acc *= SCALE;
            s[j] = acc;
            m = fmaxf(m, acc);
        }
        float sum = 0.f;
        for (int j = 0; j < Ln; j++) { s[j] = __expf(s[j] - m); sum += s[j]; }
        float o[32];
#pragma unroll
        for (int d = 0; d < 32; d++) o[d] = 0.f;
        for (int j = 0; j < Ln; j++) {
            const float* vp = g_kvb + (size_t)(b * Ln + j) * (2 * Dm) + Dm + h * DHn;
            float w = s[j];
#pragma unroll
            for (int d = 0; d < 32; d++) o[d] = fmaf(w, vp[d], o[d]);
        }
        float inv = 1.f / sum;
        float partial = 0.f;
#pragma unroll
        for (int d = 0; d < 32; d++) partial += o[d] * inv * wo[h * DHn + d];
        part[t] = partial;
    }
    __syncthreads();
    if (t < BEHn) {
        float r = 0.f;
        for (int h = 0; h < Hn; h++) r += part[t * 8 + h];
        out[b * BEHn + t] = r;
    }
}

// ---------------- spike head ----------------
__global__ void spike_kernel(const float* __restrict__ spw, const float* __restrict__ spb,
                             float* __restrict__ out) {
    int b = blockIdx.x, t = threadIdx.x;
    __shared__ float mean[Dm];
    float acc = 0.f;
    for (int l = 0; l < Ln; l++) acc += g_lat[(size_t)(b * Ln + l) * Dm + t];
    mean[t] = acc * (1.f / Ln);
    __syncthreads();
    if (t < SPKn) {
        float r = spb[t];
        for (int d = 0; d < Dm; d++) r = fmaf(mean[d], spw[d * SPKn + t], r);
        out[Bn * BEHn + b * SPKn + t] = r;
    }
}

// ---------------- host ----------------
static inline void gemm(const float* A, const float* B, const float* res, float* C,
                        int M, int N, int K, int mode) {
    int gm128 = (M + 127) / 128;
    if (gm128 * (N / 64) >= 140) {
        dim3 g(gm128, N / 64);
        gemm_kernel<<<g, 256>>>(A, B, res, C, M, N, K, mode);
    } else {
        dim3 g((M + 31) / 32, N / 64);
        gemm_kernel32<<<g, 256>>>(A, B, res, C, M, N, K, mode);
    }
}

extern "C" void kernel_launch(void* const* d_in, const int* in_sizes, int n_in,
                              void* d_out, int out_size) {
    int map[27];
    if (in_sizes[0] < 1000000) {
        for (int i = 0; i < 27; i++) map[i] = i;  // dict order
    } else {
        int m2[27] = {21,22,23,24,25,26, 0,1,2,3,4,5,6,7,8,9,10,11,12,13,14,15,16,17,18,19,20};
        for (int i = 0; i < 27; i++) map[i] = m2[i];
    }
    const int*   nid  = (const int*)  d_in[map[0]];
    const int*   tbv  = (const int*)  d_in[map[1]];
    const int*   vals = (const int*)  d_in[map[2]];
    const int*   bidx = (const int*)  d_in[map[3]];
    const float* ne   = (const float*)d_in[map[6]];
    const float* te   = (const float*)d_in[map[7]];
    const float* ve   = (const float*)d_in[map[8]];
    const float* lat0 = (const float*)d_in[map[9]];
    const float* Wq   = (const float*)d_in[map[10]];
    const float* Wkv  = (const float*)d_in[map[11]];
    const float* Wo   = (const float*)d_in[map[12]];
    const float* W1   = (const float*)d_in[map[13]];
    const float* W2   = (const float*)d_in[map[14]];
    const float* Wqkv_s = (const float*)d_in[map[15]];
    const float* Wo_s   = (const float*)d_in[map[16]];
    const float* W1_s   = (const float*)d_in[map[17]];
    const float* W2_s   = (const float*)d_in[map[18]];
    const float* bhq    = (const float*)d_in[map[19]];
    const float* bhwq   = (const float*)d_in[map[20]];
    const float* bhwkv  = (const float*)d_in[map[21]];
    const float* bhwo   = (const float*)d_in[map[22]];
    const float* lnw    = (const float*)d_in[map[23]];
    const float* lnb    = (const float*)d_in[map[24]];
    const float* spw    = (const float*)d_in[map[25]];
    const float* spb    = (const float*)d_in[map[26]];
    int E = in_sizes[map[0]];
    if (E > EMAXE) E = EMAXE;
    float* out = (float*)d_out;

    void *p_nkv, *p_tkv, *p_vkv, *p_q, *p_x, *p_qkv, *p_h, *p_ao, *p_lat, *p_kvb, *p_qb;
    cudaGetSymbolAddress(&p_nkv, g_nkv);
    cudaGetSymbolAddress(&p_tkv, g_tkv);
    cudaGetSymbolAddress(&p_vkv, g_vkv);
    cudaGetSymbolAddress(&p_q,   g_q);
    cudaGetSymbolAddress(&p_x,   g_x);
    cudaGetSymbolAddress(&p_qkv, g_qkv);
    cudaGetSymbolAddress(&p_h,   g_hbuf);
    cudaGetSymbolAddress(&p_ao,  g_ao);
    cudaGetSymbolAddress(&p_lat, g_lat);
    cudaGetSymbolAddress(&p_kvb, g_kvb);
    cudaGetSymbolAddress(&p_qb,  g_qb);
    float* f_nkv = (float*)p_nkv; float* f_tkv = (float*)p_tkv; float* f_vkv = (float*)p_vkv;
    float* f_q = (float*)p_q; float* f_x = (float*)p_x; float* f_qkv = (float*)p_qkv;
    float* f_h = (float*)p_h; float* f_ao = (float*)p_ao; float* f_lat = (float*)p_lat;
    float* f_kvb = (float*)p_kvb; float* f_qb = (float*)p_qb;

    // 1) deterministic bucket-by-batch
    hist_pass1<<<NTH / 256, 256>>>(bidx, E);
    hist_scan<<<1, 512>>>();
    scatter_pass<<<NTH / 256, 256>>>(bidx, E);

    // 2) per-event LN stats
    mustd_kernel<<<(E + 7) / 8, 256>>>(nid, tbv, vals, ne, te, ve, E);

    // 3) embedding-table KV projections
    gemm(ne, Wkv, nullptr, f_nkv, NEURONSn, 2 * Dm, Dm, 0);
    gemm(te, Wkv, nullptr, f_tkv, TBINSn,   2 * Dm, Dm, 0);
    gemm(ve, Wkv, nullptr, f_vkv, VBUCKn,   2 * Dm, Dm, 0);
    csum_kernel<<<1, 512>>>(Wkv);

    // 4) Q: LN(lat_init) @ Wq_c (shared by all batches)
    ln_kernel<<<8, 256>>>(lat0, f_x, nullptr, nullptr, Ln);
    gemm(f_x, Wq, nullptr, f_q, Ln, Dm, Dm, 0);

    // 5) cross-attention
    xattn_kernel<<<dim3(Bn, NCHUNK), 256>>>(nid, tbv, vals);
    xreduce_kernel<<<Bn * 512 / 8, 256>>>();

    // 6) residual stream
    bcast_lat<<<(Bn * Ln * Dm) / 256, 256>>>(lat0);
    gemm(f_ao, Wo, f_lat, f_lat, Bn * Ln, Dm, Dm, 1);

    // 7) cross-block MLP
    ln_kernel<<<(Bn * Ln) / 8, 256>>>(f_lat, f_x, nullptr, nullptr, Bn * Ln);
    gemm(f_x, W1, nullptr, f_h, Bn * Ln, 4 * Dm, Dm, 2);
    gemm(f_h, W2, f_lat, f_lat, Bn * Ln, Dm, 4 * Dm, 1);

    // 8) self-attention blocks
    for (int i = 0; i < NLn; i++) {
        ln_kernel<<<(Bn * Ln) / 8, 256>>>(f_lat, f_x, nullptr, nullptr, Bn * Ln);
        gemm(f_x, Wqkv_s + (size_t)i * Dm * 3 * Dm, nullptr, f_qkv, Bn * Ln, 3 * Dm, Dm, 0);
        selfattn_kernel<<<Bn * Hn, 64>>>();
        gemm(f_ao, Wo_s + (size_t)i * Dm * Dm, f_lat, f_lat, Bn * Ln, Dm, Dm, 1);
        ln_kernel<<<(Bn * Ln) / 8, 256>>>(f_lat, f_x, nullptr, nullptr, Bn * Ln);
        gemm(f_x, W1_s + (size_t)i * Dm * 4 * Dm, nullptr, f_h, Bn * Ln, 4 * Dm, Dm, 2);
        gemm(f_h, W2_s + (size_t)i * 4 * Dm * Dm, f_lat, f_lat, Bn * Ln, Dm, 4 * Dm, 1);
    }

    // 9) behavior decoder
    ln_kernel<<<(Bn * Ln) / 8, 256>>>(f_lat, f_x, lnw, lnb, Bn * Ln);
    gemm(f_x, bhwkv, nullptr, f_kvb, Bn * Ln, 2 * Dm, Dm, 0);
    gemm(bhq, bhwq, nullptr, f_qb, BEHn, Dm, Dm, 0);
    bh_kernel<<<Bn, 64>>>(bhwo, out);

    // 10) spike head
    spike_kernel<<<Bn, 256>>>(spw, spb, out);
}

// round 4
// speedup vs baseline: 2.6097x; 1.1935x over previous
#include <cuda_runtime.h>
#include <cuda_bf16.h>
#include <math.h>

// ---------------- model constants ----------------
#define Dm    256
#define Hn    8
#define DHn   32
#define Ln    64
#define BEHn  2
#define SPKn  64
#define NLn   2
#define Bn    16
#define NEURONSn 4096
#define TBINSn   1024
#define VBUCKn   256
#define EMAXC 13568
#define CHUNKE 512
#define NCHUNK 27            // 27*512 >= 13568
#define EMAXE 200000
#define NTH   2048

#define SCALE 0.17677669529663687f   // 1/sqrt(32)

typedef unsigned long long ull;

// ---------------- scratch ----------------
__device__ float g_nkv[(size_t)NEURONSn * 2 * Dm];
__device__ float g_tkv[(size_t)TBINSn   * 2 * Dm];
__device__ float g_vkv[(size_t)VBUCKn   * 2 * Dm];
__device__ float g_sn [(size_t)NEURONSn * 512];   // SCALE * (nkv_K @ q^T)
__device__ float g_st [(size_t)TBINSn   * 512];
__device__ float g_sv [(size_t)VBUCKn   * 512];
__device__ float g_qcs[512];
__device__ float g_csum[2 * Dm];
__device__ float g_mu[EMAXE];
__device__ float g_rs[EMAXE];
__device__ int4   g_eid[EMAXE];
__device__ float2 g_mr [EMAXE];
__device__ int   g_hist[NTH * Bn];
__device__ int   g_cnt[Bn];
__device__ int   g_off[Bn];
__device__ float g_psum[Bn * NCHUNK * 512];
__device__ float g_pv [(size_t)Bn * NCHUNK * 512 * 32];
__device__ float g_lnl [Ln * Dm];
__device__ float g_q   [Ln * Dm];
__device__ float g_x   [Bn * Ln * Dm];
__device__ float g_qkv [Bn * Ln * 3 * Dm];
__device__ float g_hbuf[Bn * Ln * 4 * Dm];
__device__ float g_ao  [Bn * Ln * Dm];
__device__ float g_lat [Bn * Ln * Dm];
__device__ float g_kvb [Bn * Ln * 2 * Dm];
__device__ float g_qb  [BEHn * Dm];

// ---------------- packed f32x2 helpers ----------------
__device__ __forceinline__ ull pk2(float lo, float hi) {
    ull r; asm("mov.b64 %0, {%1, %2};" : "=l"(r) : "f"(lo), "f"(hi)); return r;
}
__device__ __forceinline__ void upk2(ull v, float& lo, float& hi) {
    asm("mov.b64 {%0, %1}, %2;" : "=f"(lo), "=f"(hi) : "l"(v));
}
__device__ __forceinline__ void fma2(ull& d, ull a, ull b) {
    asm("fma.rn.f32x2 %0, %1, %2, %0;" : "+l"(d) : "l"(a), "l"(b));
}

// ---------------- device bodies ----------------
__device__ void gemm128_body(const float* __restrict__ A, const float* __restrict__ B,
                             float* __restrict__ C, int M, int N, int K, int bm, int bn) {
    __shared__ float As[16][128];
    __shared__ float Bs[16][64];
    int t = threadIdx.x;
    int ty = t >> 4, tx = t & 15;
    float acc[8][4];
#pragma unroll
    for (int i = 0; i < 8; i++)
#pragma unroll
        for (int j = 0; j < 4; j++) acc[i][j] = 0.f;
    for (int k0 = 0; k0 < K; k0 += 16) {
#pragma unroll
        for (int i = 0; i < 8; i++) {
            int idx = t + i * 256;
            int m = idx >> 4, k = idx & 15;
            int gm = bm + m;
            As[k][m] = (gm < M) ? A[(size_t)gm * K + k0 + k] : 0.f;
        }
#pragma unroll
        for (int i = 0; i < 4; i++) {
            int idx = t + i * 256;
            int k = idx >> 6, n = idx & 63;
            Bs[k][n] = B[(size_t)(k0 + k) * N + bn + n];
        }
        __syncthreads();
#pragma unroll
        for (int kk = 0; kk < 16; kk++) {
            float a[8], b4[4];
#pragma unroll
            for (int i = 0; i < 8; i++) a[i] = As[kk][ty * 8 + i];
#pragma unroll
            for (int j = 0; j < 4; j++) b4[j] = Bs[kk][tx * 4 + j];
#pragma unroll
            for (int i = 0; i < 8; i++)
#pragma unroll
                for (int j = 0; j < 4; j++) acc[i][j] = fmaf(a[i], b4[j], acc[i][j]);
        }
        __syncthreads();
    }
#pragma unroll
    for (int i = 0; i < 8; i++) {
        int gm = bm + ty * 8 + i;
        if (gm >= M) continue;
#pragma unroll
        for (int j = 0; j < 4; j++)
            C[(size_t)gm * N + bn + tx * 4 + j] = acc[i][j];
    }
}

__device__ void gemm32_body(const float* __restrict__ A, const float* __restrict__ B,
                            float* __restrict__ C, int M, int N, int K, int bm, int bn) {
    __shared__ float As2[16][32];
    __shared__ float Bs2[16][64];
    int t = threadIdx.x;
    int ty = t >> 4, tx = t & 15;
    float acc[2][4];
#pragma unroll
    for (int i = 0; i < 2; i++)
#pragma unroll
        for (int j = 0; j < 4; j++) acc[i][j] = 0.f;
    for (int k0 = 0; k0 < K; k0 += 16) {
#pragma unroll
        for (int i = 0; i < 2; i++) {
            int idx = t + i * 256;
            int m = idx >> 4, k = idx & 15;
            int gm = bm + m;
            As2[k][m] = (gm < M) ? A[(size_t)gm * K + k0 + k] : 0.f;
        }
#pragma unroll
        for (int i = 0; i < 4; i++) {
            int idx = t + i * 256;
            int k = idx >> 6, n = idx & 63;
            Bs2[k][n] = B[(size_t)(k0 + k) * N + bn + n];
        }
        __syncthreads();
#pragma unroll
        for (int kk = 0; kk < 16; kk++) {
            float a0 = As2[kk][ty * 2], a1 = As2[kk][ty * 2 + 1];
            float b4[4];
#pragma unroll
            for (int j = 0; j < 4; j++) b4[j] = Bs2[kk][tx * 4 + j];
#pragma unroll
            for (int j = 0; j < 4; j++) {
                acc[0][j] = fmaf(a0, b4[j], acc[0][j]);
                acc[1][j] = fmaf(a1, b4[j], acc[1][j]);
            }
        }
        __syncthreads();
    }
#pragma unroll
    for (int i = 0; i < 2; i++) {
        int gm = bm + ty * 2 + i;
        if (gm >= M) continue;
#pragma unroll
        for (int j = 0; j < 4; j++)
            C[(size_t)gm * N + bn + tx * 4 + j] = acc[i][j];
    }
}

// ---------------- L0: hist + csum + ln(lat0) + kv tables + mustd ----------------
#define NB_HIST 8
#define NB_CSUM 2
#define NB_LN   8
#define NB_GN   256
#define NB_GT   64
#define NB_GV   16
#define NB_FIX  (NB_HIST + NB_CSUM + NB_LN + NB_GN + NB_GT + NB_GV)   // 354

__global__ __launch_bounds__(256) void prep0_kernel(
    const int* __restrict__ bidx, const int* __restrict__ nid,
    const int* __restrict__ tb, const int* __restrict__ vv,
    const float* __restrict__ ne, const float* __restrict__ te,
    const float* __restrict__ ve, const float* __restrict__ lat0,
    const float* __restrict__ Wkv, int E) {
    int s = blockIdx.x;
    int tid = threadIdx.x;
    if (s < NB_HIST) {
        // hist
        int t = s * 256 + tid;
        int ch = (E + NTH - 1) / NTH;
        int st = t * ch, e = min(E, st + ch);
        int loc[Bn];
#pragma unroll
        for (int b = 0; b < Bn; b++) loc[b] = 0;
        for (int i = st; i < e; i++) loc[bidx[i] & (Bn - 1)]++;
#pragma unroll
        for (int b = 0; b < Bn; b++) g_hist[t * Bn + b] = loc[b];
    } else if (s < NB_HIST + NB_CSUM) {
        int x = (s - NB_HIST) * 256 + tid;
        float sum = 0.f;
        for (int k = 0; k < Dm; k++) sum += Wkv[(size_t)k * 512 + x];
        g_csum[x] = sum;
    } else if (s < NB_HIST + NB_CSUM + NB_LN) {
        // ln(lat0) -> g_lnl  (warp per row, 8 rows per block)
        int r = (s - NB_HIST - NB_CSUM) * 8 + (tid >> 5);
        int lane = tid & 31;
        const float* src = lat0 + (size_t)r * Dm;
        float v[8]; float sum = 0.f, sq = 0.f;
#pragma unroll
        for (int i = 0; i < 8; i++) {
            v[i] = src[lane + i * 32];
            sum += v[i]; sq += v[i] * v[i];
        }
#pragma unroll
        for (int o = 16; o > 0; o >>= 1) {
            sum += __shfl_xor_sync(~0u, sum, o);
            sq  += __shfl_xor_sync(~0u, sq,  o);
        }
        float mean = sum * (1.f / Dm);
        float var = sq * (1.f / Dm) - mean * mean;
        float rs = rsqrtf(var + 1e-5f);
        float* d = g_lnl + (size_t)r * Dm;
#pragma unroll
        for (int i = 0; i < 8; i++) d[lane + i * 32] = (v[i] - mean) * rs;
    } else if (s < NB_FIX) {
        int rel = s - (NB_HIST + NB_CSUM + NB_LN);
        if (rel < NB_GN) {
            gemm128_body(ne, Wkv, g_nkv, NEURONSn, 512, Dm, (rel >> 3) * 128, (rel & 7) * 64);
        } else if (rel < NB_GN + NB_GT) {
            rel -= NB_GN;
            gemm128_body(te, Wkv, g_tkv, TBINSn, 512, Dm, (rel >> 3) * 128, (rel & 7) * 64);
        } else {
            rel -= NB_GN + NB_GT;
            gemm128_body(ve, Wkv, g_vkv, VBUCKn, 512, Dm, (rel >> 3) * 128, (rel & 7) * 64);
        }
    } else {
        // mustd: warp per event
        int w = ((s - NB_FIX) * 256 + tid) >> 5;
        int lane = tid & 31;
        if (w >= E) return;
        const float* pn = ne + (size_t)nid[w] * Dm;
        const float* pt = te + (size_t)tb[w] * Dm;
        const float* pv = ve + (size_t)vv[w] * Dm;
        float sum = 0.f, sq = 0.f;
#pragma unroll
        for (int i = 0; i < 8; i++) {
            int c = lane + i * 32;
            float v = pn[c] + pt[c] + pv[c];
            sum += v; sq += v * v;
        }
#pragma unroll
        for (int o = 16; o > 0; o >>= 1) {
            sum += __shfl_xor_sync(~0u, sum, o);
            sq  += __shfl_xor_sync(~0u, sq,  o);
        }
        float mean = sum * (1.f / Dm);
        float var = sq * (1.f / Dm) - mean * mean;
        if (lane == 0) {
            g_mu[w] = mean;
            g_rs[w] = rsqrtf(var + 1e-5f);
        }
    }
}

// ---------------- L1: scan (block 0) + q gemm (blocks 1..8) ----------------
__global__ __launch_bounds__(256) void prep1_kernel(const float* __restrict__ Wq) {
    if (blockIdx.x == 0) {
        __shared__ int tot[Bn], off[Bn];
        int t = threadIdx.x;
        int w = t >> 5, lane = t & 31;
        for (int rep = 0; rep < 2; rep++) {
            int b = w * 2 + rep;
            int run = 0;
            for (int i = 0; i < NTH / 32; i++) {
                int idx = i * 32 + lane;
                int v = g_hist[idx * Bn + b];
                int incl = v;
#pragma unroll
                for (int o = 1; o < 32; o <<= 1) {
                    int u = __shfl_up_sync(~0u, incl, o);
                    if (lane >= o) incl += u;
                }
                g_hist[idx * Bn + b] = run + incl - v;
                run += __shfl_sync(~0u, incl, 31);
            }
            if (lane == 0) tot[b] = run;
        }
        __syncthreads();
        if (t == 0) {
            int r = 0;
            for (int bb = 0; bb < Bn; bb++) { off[bb] = r; r += tot[bb]; }
        }
        __syncthreads();
        for (int rep = 0; rep < 2; rep++) {
            int b = w * 2 + rep;
            int ob = off[b];
            if (lane == 0) { g_cnt[b] = tot[b]; g_off[b] = ob; }
            for (int i = 0; i < NTH / 32; i++)
                g_hist[(i * 32 + lane) * Bn + b] += ob;
        }
    } else {
        int idx = blockIdx.x - 1;   // 8 blocks: 2 m-tiles x 4 n-tiles
        gemm32_body(g_lnl, Wq, g_q, Ln, Dm, Dm, (idx >> 2) * 32, (idx & 3) * 64);
    }
}

// ---------------- L2: scatter (0..7) + score tables + qcs ----------------
#define NB_SCAT 8
#define NB_SN   256   // 4096/16
#define NB_ST   64
#define NB_SV   16

__global__ __launch_bounds__(256) void prep2_kernel(
    const int* __restrict__ bidx, const int* __restrict__ nid,
    const int* __restrict__ tb, const int* __restrict__ vv, int E) {
    int s = blockIdx.x;
    int tid = threadIdx.x;
    if (s < NB_SCAT) {
        int t = s * 256 + tid;
        int ch = (E + NTH - 1) / NTH;
        int st = t * ch, e = min(E, st + ch);
        int base[Bn];
#pragma unroll
        for (int b = 0; b < Bn; b++) base[b] = g_hist[t * Bn + b];
        for (int i = st; i < e; i++) {
            int b = bidx[i] & (Bn - 1);
            int pos = base[b]++;
            g_eid[pos] = make_int4(nid[i], tb[i], vv[i], i);
            g_mr[pos] = make_float2(g_mu[i], g_rs[i]);
        }
    } else if (s < NB_SCAT + NB_SN + NB_ST + NB_SV) {
        int rel = s - NB_SCAT;
        const float* tab; float* out; int r0;
        if (rel < NB_SN) { tab = g_nkv; out = g_sn; r0 = rel * 16; }
        else if (rel < NB_SN + NB_ST) { tab = g_tkv; out = g_st; r0 = (rel - NB_SN) * 16; }
        else { tab = g_vkv; out = g_sv; r0 = (rel - NB_SN - NB_ST) * 16; }
        __shared__ float4 sk4[16 * 64];   // 16 rows x K-half(256 floats)
        for (int i = tid; i < 16 * 64; i += 256) {
            int r = i >> 6, x = i & 63;
            sk4[i] = ((const float4*)(tab + (size_t)(r0 + r) * 512))[x];
        }
        int h = tid >> 5, li = tid & 31;
        int p0 = h * 64 + li, p1 = p0 + 32;
        ull qa[16], qb[16];
        {
            const float* q0 = g_q + (size_t)li * Dm + h * DHn;
            const float* q1 = g_q + (size_t)(li + 32) * Dm + h * DHn;
#pragma unroll
            for (int i = 0; i < 16; i++) {
                qa[i] = pk2(q0[2 * i], q0[2 * i + 1]);
                qb[i] = pk2(q1[2 * i], q1[2 * i + 1]);
            }
        }
        __syncthreads();
        for (int r = 0; r < 16; r++) {
            const float4* kk = sk4 + r * 64 + h * 8;
            ull s0a = 0ULL, s0b = 0ULL, s1a = 0ULL, s1b = 0ULL;
#pragma unroll
            for (int i = 0; i < 4; i++) {
                float4 k0 = kk[2 * i], k1 = kk[2 * i + 1];
                ull klo0 = pk2(k0.x, k0.y), khi0 = pk2(k0.z, k0.w);
                ull klo1 = pk2(k1.x, k1.y), khi1 = pk2(k1.z, k1.w);
                fma2(s0a, qa[4 * i],     klo0); fma2(s0b, qa[4 * i + 1], khi0);
                fma2(s0a, qa[4 * i + 2], klo1); fma2(s0b, qa[4 * i + 3], khi1);
                fma2(s1a, qb[4 * i],     klo0); fma2(s1b, qb[4 * i + 1], khi0);
                fma2(s1a, qb[4 * i + 2], klo1); fma2(s1b, qb[4 * i + 3], khi1);
            }
            float x0, x1, y0, y1;
            upk2(s0a, x0, x1); upk2(s0b, y0, y1);
            out[(size_t)(r0 + r) * 512 + p0] = SCALE * (x0 + x1 + y0 + y1);
            upk2(s1a, x0, x1); upk2(s1b, y0, y1);
            out[(size_t)(r0 + r) * 512 + p1] = SCALE * (x0 + x1 + y0 + y1);
        }
    } else {
        // qcs
#pragma unroll
        for (int rep = 0; rep < 2; rep++) {
            int p = tid + rep * 256;
            int h = p >> 6, l = p & 63;
            const float* qp = g_q + (size_t)l * Dm + h * DHn;
            const float* cp = g_csum + h * DHn;
            float sum = 0.f;
#pragma unroll
            for (int j = 0; j < 32; j++) sum += qp[j] * cp[j];
            g_qcs[p] = SCALE * sum;
        }
    }
}

// ---------------- L3: cross-attention (PROFILED SLOT) ----------------
// grid (Bn, NCHUNK), 256 threads; thread = (h, li) and (h, li+32)
__global__ __launch_bounds__(256) void xattn_kernel() {
    int b = blockIdx.x, c = blockIdx.y;
    int cnt = min(g_cnt[b], EMAXC);
    int start = g_off[b] + c * CHUNKE;
    int n = cnt - c * CHUNKE;
    if (n > CHUNKE) n = CHUNKE;
    if (n < 0) n = 0;

    int t = threadIdx.x;
    int h = t >> 5, li = t & 31;
    int p0 = h * 64 + li, p1 = p0 + 32;

    __shared__ float4 sv4[8 * 64];   // 8 events x V(256 floats)
    __shared__ float4 scsv[64];      // csum V-half
    if (t < 64) scsv[t] = ((const float4*)g_csum)[64 + t];

    float qc0 = g_qcs[p0], qc1 = g_qcs[p1];
    ull va[16], vb[16];
#pragma unroll
    for (int i = 0; i < 16; i++) { va[i] = 0ULL; vb[i] = 0ULL; }
    float sea = 0.f, seb = 0.f;
    __syncthreads();

    const float4* NV4 = (const float4*)g_nkv;
    const float4* TV4 = (const float4*)g_tkv;
    const float4* VV4 = (const float4*)g_vkv;

    for (int tile = 0; tile < n; tile += 8) {
        int ntile = n - tile; if (ntile > 8) ntile = 8;
        // assemble V rows from table V-halves (L2-resident)
#pragma unroll
        for (int pass = 0; pass < 2; pass++) {
            int idx = t + pass * 256;
            int e = idx >> 6, x = idx & 63;
            if (e < ntile) {
                int4 id = g_eid[start + tile + e];
                float2 mr = g_mr[start + tile + e];
                float4 a = NV4[(size_t)id.x * 128 + 64 + x];
                float4 bb = TV4[(size_t)id.y * 128 + 64 + x];
                float4 cc = VV4[(size_t)id.z * 128 + 64 + x];
                float4 cs = scsv[x];
                float4 r;
                r.x = (a.x + bb.x + cc.x - mr.x * cs.x) * mr.y;
                r.y = (a.y + bb.y + cc.y - mr.x * cs.y) * mr.y;
                r.z = (a.z + bb.z + cc.z - mr.x * cs.z) * mr.y;
                r.w = (a.w + bb.w + cc.w - mr.x * cs.w) * mr.y;
                sv4[e * 64 + x] = r;
            }
        }
        __syncthreads();
        for (int e = 0; e < ntile; e++) {
            int4 id = g_eid[start + tile + e];
            float2 mr = g_mr[start + tile + e];
            size_t rn = (size_t)id.x * 512, rt = (size_t)id.y * 512, rv = (size_t)id.z * 512;
            float s0 = g_sn[rn + p0] + g_st[rt + p0] + g_sv[rv + p0];
            float s1 = g_sn[rn + p1] + g_st[rt + p1] + g_sv[rv + p1];
            float w0 = __expf((s0 - mr.x * qc0) * mr.y);
            float w1 = __expf((s1 - mr.x * qc1) * mr.y);
            sea += w0; seb += w1;
            ull w02 = pk2(w0, w0), w12 = pk2(w1, w1);
            const float4* vr = sv4 + e * 64 + h * 8;
#pragma unroll
            for (int i = 0; i < 8; i++) {
                float4 v = vr[i];
                ull vlo = pk2(v.x, v.y), vhi = pk2(v.z, v.w);
                fma2(va[2 * i],     w02, vlo);
                fma2(va[2 * i + 1], w02, vhi);
                fma2(vb[2 * i],     w12, vlo);
                fma2(vb[2 * i + 1], w12, vhi);
            }
        }
        __syncthreads();
    }
    size_t base0 = (size_t)(b * NCHUNK + c) * 512 + p0;
    size_t base1 = (size_t)(b * NCHUNK + c) * 512 + p1;
    g_psum[base0] = sea;
    g_psum[base1] = seb;
    float* pv0 = g_pv + base0 * 32;
    float* pv1 = g_pv + base1 * 32;
#pragma unroll
    for (int i = 0; i < 16; i++) {
        float lo, hi;
        upk2(va[i], lo, hi); pv0[2 * i] = lo; pv0[2 * i + 1] = hi;
        upk2(vb[i], lo, hi); pv1[2 * i] = lo; pv1[2 * i + 1] = hi;
    }
}

// ---------------- deterministic chunk reduce ----------------
__global__ void xreduce_kernel() {
    int g = blockIdx.x * 8 + (threadIdx.x >> 5);
    int lane = threadIdx.x & 31;
    int b = g >> 9, p = g & 511;
    float vs = 0.f, ss = 0.f;
    for (int c = 0; c < NCHUNK; c++) {
        size_t base = (size_t)(b * NCHUNK + c) * 512 + p;
        ss += g_psum[base];
        vs += g_pv[base * 32 + lane];
    }
    float o = vs / ss;
    int h = p >> 6, l = p & 63;
    g_ao[(size_t)(b * Ln + l) * Dm + h * DHn + lane] = o;
}

__global__ void bcast_lat(const float* __restrict__ lat_init) {
    int i = blockIdx.x * blockDim.x + threadIdx.x;
    if (i < Bn * Ln * Dm) g_lat[i] = lat_init[i & (Ln * Dm - 1)];
}

// ---------------- LN (warp per row) ----------------
__global__ void ln_kernel(const float* __restrict__ src, float* __restrict__ dst,
                          const float* __restrict__ w, const float* __restrict__ bb, int rows) {
    int r = (blockIdx.x * blockDim.x + threadIdx.x) >> 5;
    int lane = threadIdx.x & 31;
    if (r >= rows) return;
    const float* s = src + (size_t)r * Dm;
    float v[8]; float sum = 0.f, sq = 0.f;
#pragma unroll
    for (int i = 0; i < 8; i++) {
        v[i] = s[lane + i * 32];
        sum += v[i]; sq += v[i] * v[i];
    }
#pragma unroll
    for (int o = 16; o > 0; o >>= 1) {
        sum += __shfl_xor_sync(~0u, sum, o);
        sq  += __shfl_xor_sync(~0u, sq,  o);
    }
    float mean = sum * (1.f / Dm);
    float var = sq * (1.f / Dm) - mean * mean;
    float rs = rsqrtf(var + 1e-5f);
    float* d = dst + (size_t)r * Dm;
#pragma unroll
    for (int i = 0; i < 8; i++) {
        int c = lane + i * 32;
        float y = (v[i] - mean) * rs;
        if (w) y = y * w[c] + bb[c];
        d[c] = y;
    }
}

// ---------------- standalone GEMMs (latent stack) ----------------
__global__ __launch_bounds__(256) void gemm_kernel(
    const float* __restrict__ A, const float* __restrict__ B,
    const float* __restrict__ res, float* __restrict__ C,
    int M, int N, int K, int mode) {
    __shared__ float As[16][128];
    __shared__ float Bs[16][64];
    int bm = blockIdx.x * 128, bn = blockIdx.y * 64;
    int t = threadIdx.x;
    int ty = t >> 4, tx = t & 15;
    float acc[8][4];
#pragma unroll
    for (int i = 0; i < 8; i++)
#pragma unroll
        for (int j = 0; j < 4; j++) acc[i][j] = 0.f;
    for (int k0 = 0; k0 < K; k0 += 16) {
#pragma unroll
        for (int i = 0; i < 8; i++) {
            int idx = t + i * 256;
            int m = idx >> 4, k = idx & 15;
            int gm = bm + m;
            As[k][m] = (gm < M) ? A[(size_t)gm * K + k0 + k] : 0.f;
        }
#pragma unroll
        for (int i = 0; i < 4; i++) {
            int idx = t + i * 256;
            int k = idx >> 6, n = idx & 63;
            Bs[k][n] = B[(size_t)(k0 + k) * N + bn + n];
        }
        __syncthreads();
#pragma unroll
        for (int kk = 0; kk < 16; kk++) {
            float a[8], b4[4];
#pragma unroll
            for (int i = 0; i < 8; i++) a[i] = As[kk][ty * 8 + i];
#pragma unroll
            for (int j = 0; j < 4; j++) b4[j] = Bs[kk][tx * 4 + j];
#pragma unroll
            for (int i = 0; i < 8; i++)
#pragma unroll
                for (int j = 0; j < 4; j++) acc[i][j] = fmaf(a[i], b4[j], acc[i][j]);
        }
        __syncthreads();
    }
#pragma unroll
    for (int i = 0; i < 8; i++) {
        int gm = bm + ty * 8 + i;
        if (gm >= M) continue;
#pragma unroll
        for (int j = 0; j < 4; j++) {
            int gn = bn + tx * 4 + j;
            float v = acc[i][j];
            if (mode == 1) v += res[(size_t)gm * N + gn];
            else if (mode == 2) {
                float x = v;
                v = 0.5f * x * (1.f + tanhf(0.7978845608028654f * (x + 0.044715f * x * x * x)));
            }
            C[(size_t)gm * N + gn] = v;
        }
    }
}

__global__ __launch_bounds__(256) void gemm_kernel32(
    const float* __restrict__ A, const float* __restrict__ B,
    const float* __restrict__ res, float* __restrict__ C,
    int M, int N, int K, int mode) {
    __shared__ float As[16][32];
    __shared__ float Bs[16][64];
    int bm = blockIdx.x * 32, bn = blockIdx.y * 64;
    int t = threadIdx.x;
    int ty = t >> 4, tx = t & 15;
    float acc[2][4];
#pragma unroll
    for (int i = 0; i < 2; i++)
#pragma unroll
        for (int j = 0; j < 4; j++) acc[i][j] = 0.f;
    for (int k0 = 0; k0 < K; k0 += 16) {
#pragma unroll
        for (int i = 0; i < 2; i++) {
            int idx = t + i * 256;
            int m = idx >> 4, k = idx & 15;
            int gm = bm + m;
            As[k][m] = (gm < M) ? A[(size_t)gm * K + k0 + k] : 0.f;
        }
#pragma unroll
        for (int i = 0; i < 4; i++) {
            int idx = t + i * 256;
            int k = idx >> 6, n = idx & 63;
            Bs[k][n] = B[(size_t)(k0 + k) * N + bn + n];
        }
        __syncthreads();
#pragma unroll
        for (int kk = 0; kk < 16; kk++) {
            float a0 = As[kk][ty * 2], a1 = As[kk][ty * 2 + 1];
            float b4[4];
#pragma unroll
            for (int j = 0; j < 4; j++) b4[j] = Bs[kk][tx * 4 + j];
#pragma unroll
            for (int j = 0; j < 4; j++) {
                acc[0][j] = fmaf(a0, b4[j], acc[0][j]);
                acc[1][j] = fmaf(a1, b4[j], acc[1][j]);
            }
        }
        __syncthreads();
    }
#pragma unroll
    for (int i = 0; i < 2; i++) {
        int gm = bm + ty * 2 + i;
        if (gm >= M) continue;
#pragma unroll
        for (int j = 0; j < 4; j++) {
            int gn = bn + tx * 4 + j;
            float v = acc[i][j];
            if (mode == 1) v += res[(size_t)gm * N + gn];
            else if (mode == 2) {
                float x = v;
                v = 0.5f * x * (1.f + tanhf(0.7978845608028654f * (x + 0.044715f * x * x * x)));
            }
            C[(size_t)gm * N + gn] = v;
        }
    }
}

// ---------------- self-attention ----------------
__global__ __launch_bounds__(64) void selfattn_kernel() {
    int b = blockIdx.x >> 3, h = blockIdx.x & 7;
    __shared__ float ks[Ln * DHn], vs_[Ln * DHn], sc[Ln * Ln];
    int t = threadIdx.x;
    const float* rowq = g_qkv + (size_t)(b * Ln + t) * (3 * Dm);
    float q[32];
#pragma unroll
    for (int d = 0; d < 32; d++) {
        q[d] = rowq[h * DHn + d];
        ks[t * DHn + d]  = rowq[Dm + h * DHn + d];
        vs_[t * DHn + d] = rowq[2 * Dm + h * DHn + d];
    }
    __syncthreads();
    float m = -1e30f;
    for (int j = 0; j < Ln; j++) {
        float s = 0.f;
#pragma unroll
        for (int d = 0; d < 32; d++) s = fmaf(q[d], ks[j * DHn + d], s);
        s *= SCALE;
        sc[t * Ln + j] = s;
        m = fmaxf(m, s);
    }
    float sum = 0.f;
    for (int j = 0; j < Ln; j++) {
        float w = __expf(sc[t * Ln + j] - m);
        sc[t * Ln + j] = w;
        sum += w;
    }
    float inv = 1.f / sum;
    float o[32];
#pragma unroll
    for (int d = 0; d < 32; d++) o[d] = 0.f;
    for (int j = 0; j < Ln; j++) {
        float w = sc[t * Ln + j];
#pragma unroll
        for (int d = 0; d < 32; d++) o[d] = fmaf(w, vs_[j * DHn + d], o[d]);
    }
    float* dst = g_ao + (size_t)(b * Ln + t) * Dm + h * DHn;
#pragma unroll
    for (int d = 0; d < 32; d++) dst[d] = o[d] * inv;
}

// ---------------- behavior decoder ----------------
__global__ __launch_bounds__(64) void bh_kernel(const float* __restrict__ wo, float* __restrict__ out) {
    int b = blockIdx.x, t = threadIdx.x;
    __shared__ float part[16];
    if (t < 16) {
        int qi = t >> 3, h = t & 7;
        float q[32];
#pragma unroll
        for (int d = 0; d < 32; d++) q[d] = g_qb[qi * Dm + h * DHn + d];
        float s[Ln];
        float m = -1e30f;
        for (int j = 0; j < Ln; j++) {
            const float* kp = g_kvb + (size_t)(b * Ln + j) * (2 * Dm) + h * DHn;
            float acc = 0.f;
#pragma unroll
            for (int d = 0; d < 32; d++) acc = fmaf(q[d], kp[d], acc);
            acc *= SCALE;
            s[j] = acc;
            m = fmaxf(m, acc);
        }
        float sum = 0.f;
        for (int j = 0; j < Ln; j++) { s[j] = __expf(s[j] - m); sum += s[j]; }
        float o[32];
#pragma unroll
        for (int d = 0; d < 32; d++) o[d] = 0.f;
        for (int j = 0; j < Ln; j++) {
            const float* vp = g_kvb + (size_t)(b * Ln + j) * (2 * Dm) + Dm + h * DHn;
            float w = s[j];
#pragma unroll
            for (int d = 0; d < 32; d++) o[d] = fmaf(w, vp[d], o[d]);
        }
        float inv = 1.f / sum;
        float partial = 0.f;
#pragma unroll
        for (int d = 0; d < 32; d++) partial += o[d] * inv * wo[h * DHn + d];
        part[t] = partial;
    }
    __syncthreads();
    if (t < BEHn) {
        float r = 0.f;
        for (int h = 0; h < Hn; h++) r += part[t * 8 + h];
        out[b * BEHn + t] = r;
    }
}

// ---------------- spike head ----------------
__global__ void spike_kernel(const float* __restrict__ spw, const float* __restrict__ spb,
                             float* __restrict__ out) {
    int b = blockIdx.x, t = threadIdx.x;
    __shared__ float mean[Dm];
    float acc = 0.f;
    for (int l = 0; l < Ln; l++) acc += g_lat[(size_t)(b * Ln + l) * Dm + t];
    mean[t] = acc * (1.f / Ln);
    __syncthreads();
    if (t < SPKn) {
        float r = spb[t];
        for (int d = 0; d < Dm; d++) r = fmaf(mean[d], spw[d * SPKn + t], r);
        out[Bn * BEHn + b * SPKn + t] = r;
    }
}

// ---------------- host ----------------
static inline void gemm(const float* A, const float* B, const float* res, float* C,
                        int M, int N, int K, int mode) {
    int gm128 = (M + 127) / 128;
    if (gm128 * (N / 64) >= 140) {
        dim3 g(gm128, N / 64);
        gemm_kernel<<<g, 256>>>(A, B, res, C, M, N, K, mode);
    } else {
        dim3 g((M + 31) / 32, N / 64);
        gemm_kernel32<<<g, 256>>>(A, B, res, C, M, N, K, mode);
    }
}

extern "C" void kernel_launch(void* const* d_in, const int* in_sizes, int n_in,
                              void* d_out, int out_size) {
    int map[27];
    if (in_sizes[0] < 1000000) {
        for (int i = 0; i < 27; i++) map[i] = i;  // dict order
    } else {
        int m2[27] = {21,22,23,24,25,26, 0,1,2,3,4,5,6,7,8,9,10,11,12,13,14,15,16,17,18,19,20};
        for (int i = 0; i < 27; i++) map[i] = m2[i];
    }
    const int*   nid  = (const int*)  d_in[map[0]];
    const int*   tbv  = (const int*)  d_in[map[1]];
    const int*   vals = (const int*)  d_in[map[2]];
    const int*   bidx = (const int*)  d_in[map[3]];
    const float* ne   = (const float*)d_in[map[6]];
    const float* te   = (const float*)d_in[map[7]];
    const float* ve   = (const float*)d_in[map[8]];
    const float* lat0 = (const float*)d_in[map[9]];
    const float* Wq   = (const float*)d_in[map[10]];
    const float* Wkv  = (const float*)d_in[map[11]];
    const float* Wo   = (const float*)d_in[map[12]];
    const float* W1   = (const float*)d_in[map[13]];
    const float* W2   = (const float*)d_in[map[14]];
    const float* Wqkv_s = (const float*)d_in[map[15]];
    const float* Wo_s   = (const float*)d_in[map[16]];
    const float* W1_s   = (const float*)d_in[map[17]];
    const float* W2_s   = (const float*)d_in[map[18]];
    const float* bhq    = (const float*)d_in[map[19]];
    const float* bhwq   = (const float*)d_in[map[20]];
    const float* bhwkv  = (const float*)d_in[map[21]];
    const float* bhwo   = (const float*)d_in[map[22]];
    const float* lnw    = (const float*)d_in[map[23]];
    const float* lnb    = (const float*)d_in[map[24]];
    const float* spw    = (const float*)d_in[map[25]];
    const float* spb    = (const float*)d_in[map[26]];
    int E = in_sizes[map[0]];
    if (E > EMAXE) E = EMAXE;
    float* out = (float*)d_out;

    void *p_x, *p_qkv, *p_h, *p_ao, *p_lat, *p_kvb, *p_qb;
    cudaGetSymbolAddress(&p_x,   g_x);
    cudaGetSymbolAddress(&p_qkv, g_qkv);
    cudaGetSymbolAddress(&p_h,   g_hbuf);
    cudaGetSymbolAddress(&p_ao,  g_ao);
    cudaGetSymbolAddress(&p_lat, g_lat);
    cudaGetSymbolAddress(&p_kvb, g_kvb);
    cudaGetSymbolAddress(&p_qb,  g_qb);
    float* f_x = (float*)p_x; float* f_qkv = (float*)p_qkv; float* f_h = (float*)p_h;
    float* f_ao = (float*)p_ao; float* f_lat = (float*)p_lat; float* f_kvb = (float*)p_kvb;
    float* f_qb = (float*)p_qb;

    // L0: hist + csum + ln(lat0) + kv tables + mustd
    int nb0 = NB_FIX + (E + 7) / 8;
    prep0_kernel<<<nb0, 256>>>(bidx, nid, tbv, vals, ne, te, ve, lat0, Wkv, E);
    // L1: scan + q gemm
    prep1_kernel<<<9, 256>>>(Wq);
    // L2: scatter + score tables + qcs
    prep2_kernel<<<NB_SCAT + NB_SN + NB_ST + NB_SV + 1, 256>>>(bidx, nid, tbv, vals, E);
    // L3: cross-attention (profiled slot)
    xattn_kernel<<<dim3(Bn, NCHUNK), 256>>>();
    xreduce_kernel<<<Bn * 512 / 8, 256>>>();

    // residual stream
    bcast_lat<<<(Bn * Ln * Dm) / 256, 256>>>(lat0);
    gemm(f_ao, Wo, f_lat, f_lat, Bn * Ln, Dm, Dm, 1);

    // cross-block MLP
    ln_kernel<<<(Bn * Ln) / 8, 256>>>(f_lat, f_x, nullptr, nullptr, Bn * Ln);
    gemm(f_x, W1, nullptr, f_h, Bn * Ln, 4 * Dm, Dm, 2);
    gemm(f_h, W2, f_lat, f_lat, Bn * Ln, Dm, 4 * Dm, 1);

    // self-attention blocks
    for (int i = 0; i < NLn; i++) {
        ln_kernel<<<(Bn * Ln) / 8, 256>>>(f_lat, f_x, nullptr, nullptr, Bn * Ln);
        gemm(f_x, Wqkv_s + (size_t)i * Dm * 3 * Dm, nullptr, f_qkv, Bn * Ln, 3 * Dm, Dm, 0);
        selfattn_kernel<<<Bn * Hn, 64>>>();
        gemm(f_ao, Wo_s + (size_t)i * Dm * Dm, f_lat, f_lat, Bn * Ln, Dm, Dm, 1);
        ln_kernel<<<(Bn * Ln) / 8, 256>>>(f_lat, f_x, nullptr, nullptr, Bn * Ln);
        gemm(f_x, W1_s + (size_t)i * Dm * 4 * Dm, nullptr, f_h, Bn * Ln, 4 * Dm, Dm, 2);
        gemm(f_h, W2_s + (size_t)i * 4 * Dm * Dm, f_lat, f_lat, Bn * Ln, Dm, 4 * Dm, 1);
    }

    // behavior decoder
    ln_kernel<<<(Bn * Ln) / 8, 256>>>(f_lat, f_x, lnw, lnb, Bn * Ln);
    gemm(f_x, bhwkv, nullptr, f_kvb, Bn * Ln, 2 * Dm, Dm, 0);
    gemm(bhq, bhwq, nullptr, f_qb, BEHn, Dm, Dm, 0);
    bh_kernel<<<Bn, 64>>>(bhwo, out);

    // spike head
    spike_kernel<<<Bn, 256>>>(spw, spb, out);
}